// round 14
// baseline (speedup 1.0000x reference)
#include <cuda_runtime.h>
#include <cuda_bf16.h>
#include <cstdint>
#include <cstddef>

// Problem constants (fixed by reference)
#define NNODES 30000
#define EMAX   600000
#define WIDTH  256      // heads(4) * per-head(64)
#define QKVS_W 1024     // q|k|v|s concatenated

// ================= scratch (static device globals; no allocation) ===========
__device__ __align__(16) float g_qkvs [(size_t)NNODES * QKVS_W];
__device__ __align__(16) float g_accum[(size_t)NNODES * WIDTH];
__device__ __align__(16) float g_stats[2 * WIDTH];          // sum | sumsq
__device__ int g_is64;

// CSR scratch (built once per launch; reused by both layers)
__device__ int g_deg[NNODES];
__device__ int g_off[NNODES + 1];
__device__ int g_pos[NNODES];
__device__ int g_csr[EMAX];

// bf16 split-precision scratch
__device__ __align__(16) __nv_bfloat16 g_ahi [(size_t)NNODES * 256];
__device__ __align__(16) __nv_bfloat16 g_alo [(size_t)NNODES * 256];
__device__ __align__(16) __nv_bfloat16 g_bthi[2u * 1024 * 256];   // Bt[n][k] per layer
__device__ __align__(16) __nv_bfloat16 g_btlo[2u * 1024 * 256];
__device__ __align__(16) float         g_biasc[2 * 1024];

// ================= small kernels =============================================
__global__ void __launch_bounds__(512) detect_idx_kernel(
    const int* __restrict__ ei32, int nwords) {
    __shared__ int bad;
    if (threadIdx.x == 0) bad = 0;
    __syncthreads();
    int lim = nwords < 4096 ? nwords : 4096;
    int nz = 0;
    for (int i = 1 + 2 * threadIdx.x; i < lim; i += 2 * 512)
        nz |= (ei32[i] != 0);
    if (nz) atomicOr(&bad, 1);
    __syncthreads();
    if (threadIdx.x == 0) g_is64 = !bad;
}

__device__ __forceinline__ int load_idx(const void* ei, int i) {
    if (g_is64) return (int)((const long long*)ei)[i];
    return ((const int*)ei)[i];
}

__global__ void hist_kernel(const void* __restrict__ ei, int* __restrict__ deg,
                            int E, int M) {
    int e = blockIdx.x * blockDim.x + threadIdx.x;
    if (e >= E) return;
    int dst = load_idx(ei, E + e);
    if ((unsigned)dst < (unsigned)M) atomicAdd(&deg[dst], 1);
}

__global__ void __launch_bounds__(1024) scan_kernel(
    const int* __restrict__ deg, int* __restrict__ off, int* __restrict__ pos, int n) {
    __shared__ int s[1024];
    int t = threadIdx.x;
    int chunk = (n + 1023) / 1024;
    int base = t * chunk;
    int sum = 0;
    for (int i = 0; i < chunk; i++) {
        int idx = base + i;
        if (idx < n) sum += deg[idx];
    }
    s[t] = sum;
    __syncthreads();
    for (int d = 1; d < 1024; d <<= 1) {
        int u = (t >= d) ? s[t - d] : 0;
        __syncthreads();
        s[t] += u;
        __syncthreads();
    }
    int run = s[t] - sum;
    for (int i = 0; i < chunk; i++) {
        int idx = base + i;
        if (idx < n) {
            off[idx] = run;
            pos[idx] = run;
            run += deg[idx];
        }
    }
    if (t == 1023) off[n] = s[1023];
}

__global__ void scatter_kernel(const void* __restrict__ ei, int* __restrict__ pos,
                               int* __restrict__ csr, int E, int M) {
    int e = blockIdx.x * blockDim.x + threadIdx.x;
    if (e >= E) return;
    int src = load_idx(ei, e);
    int dst = load_idx(ei, E + e);
    if ((unsigned)dst >= (unsigned)M || (unsigned)src >= (unsigned)M) return;
    int p = atomicAdd(&pos[dst], 1);
    csr[p] = src;
}

// split fp32 -> bf16 hi/lo (4 elems/thread)
__global__ void split_a_kernel(const float* __restrict__ src,
                               __nv_bfloat16* __restrict__ hi,
                               __nv_bfloat16* __restrict__ lo, int n4) {
    int i = blockIdx.x * blockDim.x + threadIdx.x;
    int s = gridDim.x * blockDim.x;
    for (; i < n4; i += s) {
        float4 v = ((const float4*)src)[i];
        __nv_bfloat16 h0 = __float2bfloat16(v.x), h1 = __float2bfloat16(v.y);
        __nv_bfloat16 h2 = __float2bfloat16(v.z), h3 = __float2bfloat16(v.w);
        __nv_bfloat16 l0 = __float2bfloat16(v.x - __bfloat162float(h0));
        __nv_bfloat16 l1 = __float2bfloat16(v.y - __bfloat162float(h1));
        __nv_bfloat16 l2 = __float2bfloat16(v.z - __bfloat162float(h2));
        __nv_bfloat16 l3 = __float2bfloat16(v.w - __bfloat162float(h3));
        ((__nv_bfloat162*)hi)[i * 2]     = __nv_bfloat162(h0, h1);
        ((__nv_bfloat162*)hi)[i * 2 + 1] = __nv_bfloat162(h2, h3);
        ((__nv_bfloat162*)lo)[i * 2]     = __nv_bfloat162(l0, l1);
        ((__nv_bfloat162*)lo)[i * 2 + 1] = __nv_bfloat162(l2, l3);
    }
}

struct WPtrs { const float* w[8]; const float* b[8]; };

__global__ void prep_weights(WPtrs P, __nv_bfloat16* __restrict__ bthi,
                             __nv_bfloat16* __restrict__ btlo) {
    const float* W = P.w[blockIdx.z];
    int layer = blockIdx.z >> 2, j = blockIdx.z & 3;
    __shared__ float t[32][33];
    int tx = threadIdx.x, ty = threadIdx.y;
    int c0 = blockIdx.x * 32, k0 = blockIdx.y * 32;
#pragma unroll
    for (int r = 0; r < 4; r++) {
        int k = k0 + ty + r * 8;
        t[ty + r * 8][tx] = W[k * 256 + c0 + tx];
    }
    __syncthreads();
#pragma unroll
    for (int r = 0; r < 4; r++) {
        int c = c0 + ty + r * 8;
        int k = k0 + tx;
        float v = t[tx][ty + r * 8];
        __nv_bfloat16 h = __float2bfloat16(v);
        size_t o = ((size_t)layer * 1024 + j * 256 + c) * 256 + k;
        bthi[o] = h;
        btlo[o] = __float2bfloat16(v - __bfloat162float(h));
    }
}

__global__ void prep_bias(WPtrs P, float* __restrict__ biasc) {
    int idx = blockIdx.x * blockDim.x + threadIdx.x;
    if (idx < 2048) {
        int layer = idx >> 10, j = (idx >> 8) & 3, c = idx & 255;
        biasc[idx] = P.b[layer * 4 + j][c];
    }
}

// == mma.sync bf16 GEMM, 2-stage cp.async, CTA 128x64, 4 warps (2x2), 2 CTA/SM =
// (R12 configuration — fastest measured)
#define KPAD 72
#define A_TILE_B (128 * KPAD)
#define B_TILE_B (64 * KPAD)
#define STAGE_B (2 * A_TILE_B + 2 * B_TILE_B)
#define SM_BYTES (2 * STAGE_B * 2)
#define GTHREADS 128

__device__ __forceinline__ void mma16816(float* d, const uint32_t* a,
                                          const uint32_t* b) {
    asm volatile(
        "mma.sync.aligned.m16n8k16.row.col.f32.bf16.bf16.f32 "
        "{%0,%1,%2,%3}, {%4,%5,%6,%7}, {%8,%9}, {%0,%1,%2,%3};"
        : "+f"(d[0]), "+f"(d[1]), "+f"(d[2]), "+f"(d[3])
        : "r"(a[0]), "r"(a[1]), "r"(a[2]), "r"(a[3]), "r"(b[0]), "r"(b[1]));
}

__device__ __forceinline__ void cpa16(uint32_t dst_s, const void* src, bool valid) {
    int sz = valid ? 16 : 0;
    asm volatile("cp.async.cg.shared.global [%0], [%1], 16, %2;"
                 :: "r"(dst_s), "l"(src), "r"(sz));
}

__device__ __forceinline__ void load_tile_a(
    uint32_t s, const __nv_bfloat16* __restrict__ g,
    int row0, int rowlim, int k0, int tid) {
#pragma unroll
    for (int it = 0; it < 8; it++) {
        int idx = it * GTHREADS + tid;
        int row = idx >> 3;
        int c8  = (idx & 7) * 8;
        int r = row0 + row;
        cpa16(s + (row * KPAD + c8) * 2, g + (size_t)r * 256 + k0 + c8, r < rowlim);
    }
}

__device__ __forceinline__ void load_tile_b(
    uint32_t s, const __nv_bfloat16* __restrict__ g, int k0, int tid) {
#pragma unroll
    for (int it = 0; it < 4; it++) {
        int idx = it * GTHREADS + tid;
        int row = idx >> 3;
        int c8  = (idx & 7) * 8;
        cpa16(s + (row * KPAD + c8) * 2, g + (size_t)row * 256 + k0 + c8, true);
    }
}

__device__ __forceinline__ void issue_stage(
    uint32_t sb, int stage,
    const __nv_bfloat16* ahi, const __nv_bfloat16* alo,
    const __nv_bfloat16* bh, const __nv_bfloat16* bl,
    int m0, int M, int k0, int tid) {
    uint32_t s = sb + stage * STAGE_B * 2;
    load_tile_a(s,                               ahi, m0, M, k0, tid);
    load_tile_a(s + A_TILE_B * 2,                alo, m0, M, k0, tid);
    load_tile_b(s + A_TILE_B * 4,                bh, k0, tid);
    load_tile_b(s + A_TILE_B * 4 + B_TILE_B * 2, bl, k0, tid);
    asm volatile("cp.async.commit_group;");
}

__global__ void __launch_bounds__(GTHREADS, 2) gemm_mma(
    const __nv_bfloat16* __restrict__ ahi, const __nv_bfloat16* __restrict__ alo,
    const __nv_bfloat16* __restrict__ bthi, const __nv_bfloat16* __restrict__ btlo,
    const float* __restrict__ bias, float* __restrict__ out, int M)
{
    extern __shared__ __align__(16) __nv_bfloat16 sm[];
    uint32_t sb = (uint32_t)__cvta_generic_to_shared(sm);

    const int tid = threadIdx.x;
    const int wid = tid >> 5, lane = tid & 31;
    const int wm = wid & 1, wn = wid >> 1;     // 2x2 warp grid
    const int g = lane >> 2, t = lane & 3;
    const int nt = blockIdx.x;                 // 0..15 : 64-col block
    const int m0 = blockIdx.y * 128;

    const __nv_bfloat16* bh = bthi + (size_t)nt * 64 * 256;
    const __nv_bfloat16* bl = btlo + (size_t)nt * 64 * 256;

    float acc[4][4][4];
#pragma unroll
    for (int i = 0; i < 4; i++)
#pragma unroll
        for (int j = 0; j < 4; j++)
#pragma unroll
            for (int k = 0; k < 4; k++) acc[i][j][k] = 0.f;

    issue_stage(sb, 0, ahi, alo, bh, bl, m0, M, 0, tid);

    for (int kc = 0; kc < 4; kc++) {
        if (kc + 1 < 4) {
            issue_stage(sb, (kc + 1) & 1, ahi, alo, bh, bl, m0, M, (kc + 1) * 64, tid);
            asm volatile("cp.async.wait_group 1;");
        } else {
            asm volatile("cp.async.wait_group 0;");
        }
        __syncthreads();

        const __nv_bfloat16* sAh = sm + (kc & 1) * STAGE_B;
        const __nv_bfloat16* sAl = sAh + A_TILE_B;
        const __nv_bfloat16* sBh = sAh + 2 * A_TILE_B;
        const __nv_bfloat16* sBl = sBh + B_TILE_B;

#pragma unroll
        for (int ks = 0; ks < 4; ks++) {
            const int kb = ks * 16 + t * 2;
            uint32_t a_h[4][4], a_l[4][4];
#pragma unroll
            for (int mf = 0; mf < 4; mf++) {
                int r = wm * 64 + mf * 16 + g;
                a_h[mf][0] = *(const uint32_t*)(sAh + r * KPAD + kb);
                a_h[mf][1] = *(const uint32_t*)(sAh + (r + 8) * KPAD + kb);
                a_h[mf][2] = *(const uint32_t*)(sAh + r * KPAD + kb + 8);
                a_h[mf][3] = *(const uint32_t*)(sAh + (r + 8) * KPAD + kb + 8);
                a_l[mf][0] = *(const uint32_t*)(sAl + r * KPAD + kb);
                a_l[mf][1] = *(const uint32_t*)(sAl + (r + 8) * KPAD + kb);
                a_l[mf][2] = *(const uint32_t*)(sAl + r * KPAD + kb + 8);
                a_l[mf][3] = *(const uint32_t*)(sAl + (r + 8) * KPAD + kb + 8);
            }
#pragma unroll
            for (int nf = 0; nf < 4; nf++) {
                int c = wn * 32 + nf * 8 + g;
                uint32_t b_h[2], b_l[2];
                b_h[0] = *(const uint32_t*)(sBh + c * KPAD + kb);
                b_h[1] = *(const uint32_t*)(sBh + c * KPAD + kb + 8);
                b_l[0] = *(const uint32_t*)(sBl + c * KPAD + kb);
                b_l[1] = *(const uint32_t*)(sBl + c * KPAD + kb + 8);
#pragma unroll
                for (int mf = 0; mf < 4; mf++) {
                    mma16816(acc[mf][nf], a_h[mf], b_h);
                    mma16816(acc[mf][nf], a_h[mf], b_l);
                    mma16816(acc[mf][nf], a_l[mf], b_h);
                }
            }
        }
        __syncthreads();
    }

#pragma unroll
    for (int mf = 0; mf < 4; mf++) {
        int r0 = m0 + wm * 64 + mf * 16 + g;
#pragma unroll
        for (int nf = 0; nf < 4; nf++) {
            int cg = nt * 64 + wn * 32 + nf * 8 + t * 2;
            float bx = bias[cg], by = bias[cg + 1];
            if (r0 < M) {
                float2 o = make_float2(acc[mf][nf][0] + bx, acc[mf][nf][1] + by);
                *(float2*)(out + (size_t)r0 * QKVS_W + cg) = o;
            }
            if (r0 + 8 < M) {
                float2 o = make_float2(acc[mf][nf][2] + bx, acc[mf][nf][3] + by);
                *(float2*)(out + (size_t)(r0 + 8) * QKVS_W + cg) = o;
            }
        }
    }
}

// ======= gather edge aggregation: 4-edge unroll, barrier-free ===============
__global__ void __launch_bounds__(256) edge_agg(
    const float* __restrict__ qkvs,
    const int* __restrict__ off, const int* __restrict__ csr,
    float* __restrict__ accum, int M)
{
    int warp = (blockIdx.x * blockDim.x + threadIdx.x) >> 5;
    int lane = threadIdx.x & 31;
    if (warp >= M) return;

    const float4* qp = (const float4*)(qkvs + (size_t)warp * QKVS_W);
    float4 q0 = __ldg(&qp[lane * 2]), q1 = __ldg(&qp[lane * 2 + 1]);

    int i0 = off[warp], i1 = off[warp + 1];
    float a0x = 0.f, a0y = 0.f, a0z = 0.f, a0w = 0.f;
    float a1x = 0.f, a1y = 0.f, a1z = 0.f, a1w = 0.f;
    float dsum = 0.f;

    int i = i0;
    for (; i + 4 <= i1; i += 4) {
        float4 k0[4], k1[4], v0[4], v1[4];
#pragma unroll
        for (int e = 0; e < 4; e++) {
            int s = __ldg(&csr[i + e]);
            const float4* kp = (const float4*)(qkvs + (size_t)s * QKVS_W + 256);
            const float4* vp = (const float4*)(qkvs + (size_t)s * QKVS_W + 512);
            k0[e] = __ldg(&kp[lane * 2]); k1[e] = __ldg(&kp[lane * 2 + 1]);
            v0[e] = __ldg(&vp[lane * 2]); v1[e] = __ldg(&vp[lane * 2 + 1]);
        }
        float p[4];
#pragma unroll
        for (int e = 0; e < 4; e++)
            p[e] = q0.x * k0[e].x + q0.y * k0[e].y + q0.z * k0[e].z + q0.w * k0[e].w
                 + q1.x * k1[e].x + q1.y * k1[e].y + q1.z * k1[e].z + q1.w * k1[e].w;
#pragma unroll
        for (int e = 0; e < 4; e++) p[e] += __shfl_xor_sync(0xffffffffu, p[e], 1);
#pragma unroll
        for (int e = 0; e < 4; e++) p[e] += __shfl_xor_sync(0xffffffffu, p[e], 2);
#pragma unroll
        for (int e = 0; e < 4; e++) p[e] += __shfl_xor_sync(0xffffffffu, p[e], 4);
#pragma unroll
        for (int e = 0; e < 4; e++) {
            float ex = __expf(p[e] * 0.125f);
            dsum += ex;
            a0x += v0[e].x * ex; a0y += v0[e].y * ex;
            a0z += v0[e].z * ex; a0w += v0[e].w * ex;
            a1x += v1[e].x * ex; a1y += v1[e].y * ex;
            a1z += v1[e].z * ex; a1w += v1[e].w * ex;
        }
    }
    for (; i < i1; i++) {
        int s = __ldg(&csr[i]);
        const float4* kp = (const float4*)(qkvs + (size_t)s * QKVS_W + 256);
        const float4* vp = (const float4*)(qkvs + (size_t)s * QKVS_W + 512);
        float4 k0 = __ldg(&kp[lane * 2]), k1 = __ldg(&kp[lane * 2 + 1]);
        float4 v0 = __ldg(&vp[lane * 2]), v1 = __ldg(&vp[lane * 2 + 1]);
        float p = q0.x * k0.x + q0.y * k0.y + q0.z * k0.z + q0.w * k0.w
                + q1.x * k1.x + q1.y * k1.y + q1.z * k1.z + q1.w * k1.w;
        p += __shfl_xor_sync(0xffffffffu, p, 1);
        p += __shfl_xor_sync(0xffffffffu, p, 2);
        p += __shfl_xor_sync(0xffffffffu, p, 4);
        float ex = __expf(p * 0.125f);
        dsum += ex;
        a0x += v0.x * ex; a0y += v0.y * ex; a0z += v0.z * ex; a0w += v0.w * ex;
        a1x += v1.x * ex; a1y += v1.y * ex; a1z += v1.z * ex; a1w += v1.w * ex;
    }

    float inv = (dsum > 0.f) ? (1.0f / dsum) : 0.f;
    const float4* sp = (const float4*)(qkvs + (size_t)warp * QKVS_W + 768);
    float4 s0 = __ldg(&sp[lane * 2]), s1 = __ldg(&sp[lane * 2 + 1]);
    float4 o0 = make_float4(a0x * inv + s0.x, a0y * inv + s0.y,
                            a0z * inv + s0.z, a0w * inv + s0.w);
    float4 o1 = make_float4(a1x * inv + s1.x, a1y * inv + s1.y,
                            a1z * inv + s1.z, a1w * inv + s1.w);
    float4* op = (float4*)(accum + (size_t)warp * WIDTH + lane * 8);
    op[0] = o0;
    op[1] = o1;
}

// ================= BN stats ==================================================
#define FIN_ROWS 32
__global__ void __launch_bounds__(256) stats_kernel(
    const float* __restrict__ accum, float* __restrict__ stats, int M)
{
    const int c = threadIdx.x;
    const int r0 = blockIdx.x * FIN_ROWS;
    float s1 = 0.f, s2 = 0.f;
#pragma unroll 4
    for (int r = 0; r < FIN_ROWS; r++) {
        int n = r0 + r;
        if (n >= M) break;
        float v = accum[(size_t)n * WIDTH + c];
        s1 += v; s2 += v * v;
    }
    atomicAdd(&stats[c], s1);
    atomicAdd(&stats[WIDTH + c], s2);
}

__global__ void __launch_bounds__(256) bn_act(
    const float* __restrict__ in, const float* __restrict__ stats,
    const float* __restrict__ gamma, const float* __restrict__ beta,
    float* __restrict__ out, int M, float invN)
{
    int idx = blockIdx.x * blockDim.x + threadIdx.x;
    int total = M * WIDTH;
    int stride = gridDim.x * blockDim.x;
    for (; idx < total; idx += stride) {
        int c = idx & (WIDTH - 1);
        float mean = stats[c] * invN;
        float var  = stats[WIDTH + c] * invN - mean * mean;
        float sc = rsqrtf(var + 1e-5f) * gamma[c];
        float sh = beta[c] - mean * sc;
        float v = in[idx] * sc + sh;
        out[idx] = (v >= 0.f) ? v : 0.1f * v;
    }
}

// BN + leaky-relu + bf16 hi/lo split, feeding the next GEMM directly
__global__ void __launch_bounds__(256) bn_act_split(
    const float* __restrict__ in, const float* __restrict__ stats,
    const float* __restrict__ gamma, const float* __restrict__ beta,
    __nv_bfloat16* __restrict__ hi, __nv_bfloat16* __restrict__ lo,
    int n4, float invN)
{
    int i = blockIdx.x * blockDim.x + threadIdx.x;
    int stride = gridDim.x * blockDim.x;
    for (; i < n4; i += stride) {
        int c = (i & 63) * 4;
        float4 v = ((const float4*)in)[i];
        float r[4] = {v.x, v.y, v.z, v.w};
        __nv_bfloat16 hh[4], ll[4];
#pragma unroll
        for (int j = 0; j < 4; j++) {
            int cc = c + j;
            float mean = stats[cc] * invN;
            float var  = stats[WIDTH + cc] * invN - mean * mean;
            float sc = rsqrtf(var + 1e-5f) * gamma[cc];
            float sh = beta[cc] - mean * sc;
            float x = r[j] * sc + sh;
            x = (x >= 0.f) ? x : 0.1f * x;
            hh[j] = __float2bfloat16(x);
            ll[j] = __float2bfloat16(x - __bfloat162float(hh[j]));
        }
        ((__nv_bfloat162*)hi)[i * 2]     = __nv_bfloat162(hh[0], hh[1]);
        ((__nv_bfloat162*)hi)[i * 2 + 1] = __nv_bfloat162(hh[2], hh[3]);
        ((__nv_bfloat162*)lo)[i * 2]     = __nv_bfloat162(ll[0], ll[1]);
        ((__nv_bfloat162*)lo)[i * 2 + 1] = __nv_bfloat162(ll[2], ll[3]);
    }
}

// ================= launch ====================================================
extern "C" void kernel_launch(void* const* d_in, const int* in_sizes, int n_in,
                              void* d_out, int out_size)
{
    const float* x  = (const float*)d_in[0];
    const void*  ei = d_in[1];
    WPtrs wp;
    for (int i = 0; i < 4; i++) {
        wp.w[i]     = (const float*)d_in[2 + i * 2];
        wp.b[i]     = (const float*)d_in[3 + i * 2];
        wp.w[4 + i] = (const float*)d_in[12 + i * 2];
        wp.b[4 + i] = (const float*)d_in[13 + i * 2];
    }
    const float* g1  = (const float*)d_in[10]; const float* be1 = (const float*)d_in[11];
    const float* g2  = (const float*)d_in[20]; const float* be2 = (const float*)d_in[21];

    const int M = in_sizes[0] / WIDTH;   // 30000
    const int E = in_sizes[1] / 2;       // 600000

    float *qkvs, *accum, *stats, *biasc;
    __nv_bfloat16 *ahi, *alo, *bthi, *btlo;
    int *deg, *off, *pos, *csr;
    cudaGetSymbolAddress((void**)&qkvs,  g_qkvs);
    cudaGetSymbolAddress((void**)&accum, g_accum);
    cudaGetSymbolAddress((void**)&stats, g_stats);
    cudaGetSymbolAddress((void**)&ahi,   g_ahi);
    cudaGetSymbolAddress((void**)&alo,   g_alo);
    cudaGetSymbolAddress((void**)&bthi,  g_bthi);
    cudaGetSymbolAddress((void**)&btlo,  g_btlo);
    cudaGetSymbolAddress((void**)&biasc, g_biasc);
    cudaGetSymbolAddress((void**)&deg,   g_deg);
    cudaGetSymbolAddress((void**)&off,   g_off);
    cudaGetSymbolAddress((void**)&pos,   g_pos);
    cudaGetSymbolAddress((void**)&csr,   g_csr);

    cudaFuncSetAttribute(gemm_mma, cudaFuncAttributeMaxDynamicSharedMemorySize, SM_BYTES);

    dim3 ggrid(16, (M + 127) / 128);
    int eb = (E + 255) / 256;
    int agg_blocks  = (M * 32 + 255) / 256;
    int stat_blocks = (M + FIN_ROWS - 1) / FIN_ROWS;
    float invN = 1.0f / (float)M;

    // ---- prep (once, single stream) ----
    detect_idx_kernel<<<1, 512>>>((const int*)ei, 2 * E);
    prep_weights<<<dim3(8, 8, 8), dim3(32, 8)>>>(wp, bthi, btlo);
    prep_bias<<<8, 256>>>(wp, biasc);

    // ---- CSR build (once) ----
    cudaMemsetAsync(deg, 0, M * sizeof(int));
    hist_kernel<<<eb, 256>>>(ei, deg, E, M);
    scan_kernel<<<1, 1024>>>(deg, off, pos, M);
    scatter_kernel<<<eb, 256>>>(ei, pos, csr, E, M);

    // ---- layer 1 ----
    split_a_kernel<<<960, 512>>>(x, ahi, alo, M * 64);
    gemm_mma<<<ggrid, GTHREADS, SM_BYTES>>>(ahi, alo, bthi, btlo, biasc, qkvs, M);
    edge_agg<<<agg_blocks, 256>>>(qkvs, off, csr, accum, M);
    cudaMemsetAsync(stats, 0, 2 * WIDTH * sizeof(float));
    stats_kernel<<<stat_blocks, 256>>>(accum, stats, M);
    bn_act_split<<<480, 256>>>(accum, stats, g1, be1, ahi, alo, M * 64, invN);

    // ---- layer 2 ----
    gemm_mma<<<ggrid, GTHREADS, SM_BYTES>>>(ahi, alo, bthi + (size_t)1024 * 256,
                                            btlo + (size_t)1024 * 256, biasc + 1024, qkvs, M);
    edge_agg<<<agg_blocks, 256>>>(qkvs, off, csr, accum, M);
    cudaMemsetAsync(stats, 0, 2 * WIDTH * sizeof(float));
    stats_kernel<<<stat_blocks, 256>>>(accum, stats, M);
    bn_act<<<480, 256>>>(accum, stats, g2, be2, (float*)d_out, M, invN);
}

// round 15
// speedup vs baseline: 1.5367x; 1.5367x over previous
#include <cuda_runtime.h>
#include <cuda_bf16.h>
#include <cstdint>
#include <cstddef>

// Problem constants (fixed by reference)
#define NNODES 30000
#define EMAX   600000
#define WIDTH  256      // heads(4) * per-head(64)
#define QKVS_W 1024     // q|k|v|s concatenated

// ================= scratch (static device globals; no allocation) ===========
__device__ __align__(16) float g_qkvs [(size_t)NNODES * QKVS_W];
__device__ __align__(16) float g_accum[(size_t)NNODES * WIDTH];
__device__ __align__(16) float g_stats[2 * WIDTH];          // sum | sumsq
__device__ int g_is64;

// CSR scratch (built once per launch; reused by both layers)
__device__ int g_deg[NNODES];
__device__ int g_off[NNODES + 1];
__device__ int g_pos[NNODES];
__device__ int g_csr[EMAX];

// bf16 split-precision scratch
__device__ __align__(16) __nv_bfloat16 g_ahi [(size_t)NNODES * 256];
__device__ __align__(16) __nv_bfloat16 g_alo [(size_t)NNODES * 256];
__device__ __align__(16) __nv_bfloat16 g_bthi[2u * 1024 * 256];   // Bt[n][k] per layer
__device__ __align__(16) __nv_bfloat16 g_btlo[2u * 1024 * 256];
__device__ __align__(16) float         g_biasc[2 * 1024];

// ================= small kernels =============================================
__global__ void __launch_bounds__(512) detect_idx_kernel(
    const int* __restrict__ ei32, int nwords) {
    __shared__ int bad;
    if (threadIdx.x == 0) bad = 0;
    __syncthreads();
    int lim = nwords < 4096 ? nwords : 4096;
    int nz = 0;
    for (int i = 1 + 2 * threadIdx.x; i < lim; i += 2 * 512)
        nz |= (ei32[i] != 0);
    if (nz) atomicOr(&bad, 1);
    __syncthreads();
    if (threadIdx.x == 0) g_is64 = !bad;
}

__device__ __forceinline__ int load_idx(const void* ei, int i) {
    if (g_is64) return (int)((const long long*)ei)[i];
    return ((const int*)ei)[i];
}

__global__ void hist_kernel(const void* __restrict__ ei, int* __restrict__ deg,
                            int E, int M) {
    int e = blockIdx.x * blockDim.x + threadIdx.x;
    if (e >= E) return;
    int dst = load_idx(ei, E + e);
    if ((unsigned)dst < (unsigned)M) atomicAdd(&deg[dst], 1);
}

__global__ void __launch_bounds__(1024) scan_kernel(
    const int* __restrict__ deg, int* __restrict__ off, int* __restrict__ pos, int n) {
    __shared__ int s[1024];
    int t = threadIdx.x;
    int chunk = (n + 1023) / 1024;
    int base = t * chunk;
    int sum = 0;
    for (int i = 0; i < chunk; i++) {
        int idx = base + i;
        if (idx < n) sum += deg[idx];
    }
    s[t] = sum;
    __syncthreads();
    for (int d = 1; d < 1024; d <<= 1) {
        int u = (t >= d) ? s[t - d] : 0;
        __syncthreads();
        s[t] += u;
        __syncthreads();
    }
    int run = s[t] - sum;
    for (int i = 0; i < chunk; i++) {
        int idx = base + i;
        if (idx < n) {
            off[idx] = run;
            pos[idx] = run;
            run += deg[idx];
        }
    }
    if (t == 1023) off[n] = s[1023];
}

__global__ void scatter_kernel(const void* __restrict__ ei, int* __restrict__ pos,
                               int* __restrict__ csr, int E, int M) {
    int e = blockIdx.x * blockDim.x + threadIdx.x;
    if (e >= E) return;
    int src = load_idx(ei, e);
    int dst = load_idx(ei, E + e);
    if ((unsigned)dst >= (unsigned)M || (unsigned)src >= (unsigned)M) return;
    int p = atomicAdd(&pos[dst], 1);
    csr[p] = src;
}

// split fp32 -> bf16 hi/lo (4 elems/thread)
__global__ void split_a_kernel(const float* __restrict__ src,
                               __nv_bfloat16* __restrict__ hi,
                               __nv_bfloat16* __restrict__ lo, int n4) {
    int i = blockIdx.x * blockDim.x + threadIdx.x;
    int s = gridDim.x * blockDim.x;
    for (; i < n4; i += s) {
        float4 v = ((const float4*)src)[i];
        __nv_bfloat16 h0 = __float2bfloat16(v.x), h1 = __float2bfloat16(v.y);
        __nv_bfloat16 h2 = __float2bfloat16(v.z), h3 = __float2bfloat16(v.w);
        __nv_bfloat16 l0 = __float2bfloat16(v.x - __bfloat162float(h0));
        __nv_bfloat16 l1 = __float2bfloat16(v.y - __bfloat162float(h1));
        __nv_bfloat16 l2 = __float2bfloat16(v.z - __bfloat162float(h2));
        __nv_bfloat16 l3 = __float2bfloat16(v.w - __bfloat162float(h3));
        ((__nv_bfloat162*)hi)[i * 2]     = __nv_bfloat162(h0, h1);
        ((__nv_bfloat162*)hi)[i * 2 + 1] = __nv_bfloat162(h2, h3);
        ((__nv_bfloat162*)lo)[i * 2]     = __nv_bfloat162(l0, l1);
        ((__nv_bfloat162*)lo)[i * 2 + 1] = __nv_bfloat162(l2, l3);
    }
}

struct WPtrs { const float* w[8]; const float* b[8]; };

__global__ void prep_weights(WPtrs P, __nv_bfloat16* __restrict__ bthi,
                             __nv_bfloat16* __restrict__ btlo) {
    const float* W = P.w[blockIdx.z];
    int layer = blockIdx.z >> 2, j = blockIdx.z & 3;
    __shared__ float t[32][33];
    int tx = threadIdx.x, ty = threadIdx.y;
    int c0 = blockIdx.x * 32, k0 = blockIdx.y * 32;
#pragma unroll
    for (int r = 0; r < 4; r++) {
        int k = k0 + ty + r * 8;
        t[ty + r * 8][tx] = W[k * 256 + c0 + tx];
    }
    __syncthreads();
#pragma unroll
    for (int r = 0; r < 4; r++) {
        int c = c0 + ty + r * 8;
        int k = k0 + tx;
        float v = t[tx][ty + r * 8];
        __nv_bfloat16 h = __float2bfloat16(v);
        size_t o = ((size_t)layer * 1024 + j * 256 + c) * 256 + k;
        bthi[o] = h;
        btlo[o] = __float2bfloat16(v - __bfloat162float(h));
    }
}

__global__ void prep_bias(WPtrs P, float* __restrict__ biasc) {
    int idx = blockIdx.x * blockDim.x + threadIdx.x;
    if (idx < 2048) {
        int layer = idx >> 10, j = (idx >> 8) & 3, c = idx & 255;
        biasc[idx] = P.b[layer * 4 + j][c];
    }
}

// == mma.sync bf16 GEMM, 2-stage cp.async, CTA 128x64, 4 warps (2x2), 2 CTA/SM =
#define KPAD 72
#define A_TILE_B (128 * KPAD)
#define B_TILE_B (64 * KPAD)
#define STAGE_B (2 * A_TILE_B + 2 * B_TILE_B)
#define SM_BYTES (2 * STAGE_B * 2)
#define GTHREADS 128

__device__ __forceinline__ void mma16816(float* d, const uint32_t* a,
                                          const uint32_t* b) {
    asm volatile(
        "mma.sync.aligned.m16n8k16.row.col.f32.bf16.bf16.f32 "
        "{%0,%1,%2,%3}, {%4,%5,%6,%7}, {%8,%9}, {%0,%1,%2,%3};"
        : "+f"(d[0]), "+f"(d[1]), "+f"(d[2]), "+f"(d[3])
        : "r"(a[0]), "r"(a[1]), "r"(a[2]), "r"(a[3]), "r"(b[0]), "r"(b[1]));
}

__device__ __forceinline__ void cpa16(uint32_t dst_s, const void* src, bool valid) {
    int sz = valid ? 16 : 0;
    asm volatile("cp.async.cg.shared.global [%0], [%1], 16, %2;"
                 :: "r"(dst_s), "l"(src), "r"(sz));
}

__device__ __forceinline__ void load_tile_a(
    uint32_t s, const __nv_bfloat16* __restrict__ g,
    int row0, int rowlim, int k0, int tid) {
#pragma unroll
    for (int it = 0; it < 8; it++) {
        int idx = it * GTHREADS + tid;
        int row = idx >> 3;
        int c8  = (idx & 7) * 8;
        int r = row0 + row;
        cpa16(s + (row * KPAD + c8) * 2, g + (size_t)r * 256 + k0 + c8, r < rowlim);
    }
}

__device__ __forceinline__ void load_tile_b(
    uint32_t s, const __nv_bfloat16* __restrict__ g, int k0, int tid) {
#pragma unroll
    for (int it = 0; it < 4; it++) {
        int idx = it * GTHREADS + tid;
        int row = idx >> 3;
        int c8  = (idx & 7) * 8;
        cpa16(s + (row * KPAD + c8) * 2, g + (size_t)row * 256 + k0 + c8, true);
    }
}

__device__ __forceinline__ void issue_stage(
    uint32_t sb, int stage,
    const __nv_bfloat16* ahi, const __nv_bfloat16* alo,
    const __nv_bfloat16* bh, const __nv_bfloat16* bl,
    int m0, int M, int k0, int tid) {
    uint32_t s = sb + stage * STAGE_B * 2;
    load_tile_a(s,                               ahi, m0, M, k0, tid);
    load_tile_a(s + A_TILE_B * 2,                alo, m0, M, k0, tid);
    load_tile_b(s + A_TILE_B * 4,                bh, k0, tid);
    load_tile_b(s + A_TILE_B * 4 + B_TILE_B * 2, bl, k0, tid);
    asm volatile("cp.async.commit_group;");
}

__global__ void __launch_bounds__(GTHREADS, 2) gemm_mma(
    const __nv_bfloat16* __restrict__ ahi, const __nv_bfloat16* __restrict__ alo,
    const __nv_bfloat16* __restrict__ bthi, const __nv_bfloat16* __restrict__ btlo,
    const float* __restrict__ bias, float* __restrict__ out, int M)
{
    extern __shared__ __align__(16) __nv_bfloat16 sm[];
    uint32_t sb = (uint32_t)__cvta_generic_to_shared(sm);

    const int tid = threadIdx.x;
    const int wid = tid >> 5, lane = tid & 31;
    const int wm = wid & 1, wn = wid >> 1;     // 2x2 warp grid
    const int g = lane >> 2, t = lane & 3;
    const int nt = blockIdx.x;                 // 0..15 : 64-col block
    const int m0 = blockIdx.y * 128;

    const __nv_bfloat16* bh = bthi + (size_t)nt * 64 * 256;
    const __nv_bfloat16* bl = btlo + (size_t)nt * 64 * 256;

    float acc[4][4][4];
#pragma unroll
    for (int i = 0; i < 4; i++)
#pragma unroll
        for (int j = 0; j < 4; j++)
#pragma unroll
            for (int k = 0; k < 4; k++) acc[i][j][k] = 0.f;

    issue_stage(sb, 0, ahi, alo, bh, bl, m0, M, 0, tid);

    for (int kc = 0; kc < 4; kc++) {
        if (kc + 1 < 4) {
            issue_stage(sb, (kc + 1) & 1, ahi, alo, bh, bl, m0, M, (kc + 1) * 64, tid);
            asm volatile("cp.async.wait_group 1;");
        } else {
            asm volatile("cp.async.wait_group 0;");
        }
        __syncthreads();

        const __nv_bfloat16* sAh = sm + (kc & 1) * STAGE_B;
        const __nv_bfloat16* sAl = sAh + A_TILE_B;
        const __nv_bfloat16* sBh = sAh + 2 * A_TILE_B;
        const __nv_bfloat16* sBl = sBh + B_TILE_B;

#pragma unroll
        for (int ks = 0; ks < 4; ks++) {
            const int kb = ks * 16 + t * 2;
            uint32_t a_h[4][4], a_l[4][4];
#pragma unroll
            for (int mf = 0; mf < 4; mf++) {
                int r = wm * 64 + mf * 16 + g;
                a_h[mf][0] = *(const uint32_t*)(sAh + r * KPAD + kb);
                a_h[mf][1] = *(const uint32_t*)(sAh + (r + 8) * KPAD + kb);
                a_h[mf][2] = *(const uint32_t*)(sAh + r * KPAD + kb + 8);
                a_h[mf][3] = *(const uint32_t*)(sAh + (r + 8) * KPAD + kb + 8);
                a_l[mf][0] = *(const uint32_t*)(sAl + r * KPAD + kb);
                a_l[mf][1] = *(const uint32_t*)(sAl + (r + 8) * KPAD + kb);
                a_l[mf][2] = *(const uint32_t*)(sAl + r * KPAD + kb + 8);
                a_l[mf][3] = *(const uint32_t*)(sAl + (r + 8) * KPAD + kb + 8);
            }
#pragma unroll
            for (int nf = 0; nf < 4; nf++) {
                int c = wn * 32 + nf * 8 + g;
                uint32_t b_h[2], b_l[2];
                b_h[0] = *(const uint32_t*)(sBh + c * KPAD + kb);
                b_h[1] = *(const uint32_t*)(sBh + c * KPAD + kb + 8);
                b_l[0] = *(const uint32_t*)(sBl + c * KPAD + kb);
                b_l[1] = *(const uint32_t*)(sBl + c * KPAD + kb + 8);
#pragma unroll
                for (int mf = 0; mf < 4; mf++) {
                    mma16816(acc[mf][nf], a_h[mf], b_h);
                    mma16816(acc[mf][nf], a_h[mf], b_l);
                    mma16816(acc[mf][nf], a_l[mf], b_h);
                }
            }
        }
        __syncthreads();
    }

#pragma unroll
    for (int mf = 0; mf < 4; mf++) {
        int r0 = m0 + wm * 64 + mf * 16 + g;
#pragma unroll
        for (int nf = 0; nf < 4; nf++) {
            int cg = nt * 64 + wn * 32 + nf * 8 + t * 2;
            float bx = bias[cg], by = bias[cg + 1];
            if (r0 < M) {
                float2 o = make_float2(acc[mf][nf][0] + bx, acc[mf][nf][1] + by);
                *(float2*)(out + (size_t)r0 * QKVS_W + cg) = o;
            }
            if (r0 + 8 < M) {
                float2 o = make_float2(acc[mf][nf][2] + bx, acc[mf][nf][3] + by);
                *(float2*)(out + (size_t)(r0 + 8) * QKVS_W + cg) = o;
            }
        }
    }
}

// ======= gather edge aggregation (2-edge unroll, barrier-free) ==============
__global__ void __launch_bounds__(256) edge_agg(
    const float* __restrict__ qkvs,
    const int* __restrict__ off, const int* __restrict__ csr,
    float* __restrict__ accum, int M)
{
    int warp = (blockIdx.x * blockDim.x + threadIdx.x) >> 5;
    int lane = threadIdx.x & 31;
    if (warp >= M) return;

    const float4* qp = (const float4*)(qkvs + (size_t)warp * QKVS_W);
    float4 q0 = __ldg(&qp[lane * 2]), q1 = __ldg(&qp[lane * 2 + 1]);

    int i0 = off[warp], i1 = off[warp + 1];
    float a0x = 0.f, a0y = 0.f, a0z = 0.f, a0w = 0.f;
    float a1x = 0.f, a1y = 0.f, a1z = 0.f, a1w = 0.f;
    float dsum = 0.f;

    int i = i0;
    for (; i + 2 <= i1; i += 2) {
        int sa = __ldg(&csr[i]), sb = __ldg(&csr[i + 1]);
        const float4* kpa = (const float4*)(qkvs + (size_t)sa * QKVS_W + 256);
        const float4* vpa = (const float4*)(qkvs + (size_t)sa * QKVS_W + 512);
        const float4* kpb = (const float4*)(qkvs + (size_t)sb * QKVS_W + 256);
        const float4* vpb = (const float4*)(qkvs + (size_t)sb * QKVS_W + 512);
        float4 ka0 = __ldg(&kpa[lane * 2]), ka1 = __ldg(&kpa[lane * 2 + 1]);
        float4 kb0 = __ldg(&kpb[lane * 2]), kb1 = __ldg(&kpb[lane * 2 + 1]);
        float4 va0 = __ldg(&vpa[lane * 2]), va1 = __ldg(&vpa[lane * 2 + 1]);
        float4 vb0 = __ldg(&vpb[lane * 2]), vb1 = __ldg(&vpb[lane * 2 + 1]);

        float pa = q0.x * ka0.x + q0.y * ka0.y + q0.z * ka0.z + q0.w * ka0.w
                 + q1.x * ka1.x + q1.y * ka1.y + q1.z * ka1.z + q1.w * ka1.w;
        float pb = q0.x * kb0.x + q0.y * kb0.y + q0.z * kb0.z + q0.w * kb0.w
                 + q1.x * kb1.x + q1.y * kb1.y + q1.z * kb1.z + q1.w * kb1.w;
        pa += __shfl_xor_sync(0xffffffffu, pa, 1);
        pb += __shfl_xor_sync(0xffffffffu, pb, 1);
        pa += __shfl_xor_sync(0xffffffffu, pa, 2);
        pb += __shfl_xor_sync(0xffffffffu, pb, 2);
        pa += __shfl_xor_sync(0xffffffffu, pa, 4);
        pb += __shfl_xor_sync(0xffffffffu, pb, 4);
        float exa = __expf(pa * 0.125f);
        float exb = __expf(pb * 0.125f);
        dsum += exa + exb;
        a0x += va0.x * exa + vb0.x * exb; a0y += va0.y * exa + vb0.y * exb;
        a0z += va0.z * exa + vb0.z * exb; a0w += va0.w * exa + vb0.w * exb;
        a1x += va1.x * exa + vb1.x * exb; a1y += va1.y * exa + vb1.y * exb;
        a1z += va1.z * exa + vb1.z * exb; a1w += va1.w * exa + vb1.w * exb;
    }
    if (i < i1) {
        int s = __ldg(&csr[i]);
        const float4* kp = (const float4*)(qkvs + (size_t)s * QKVS_W + 256);
        const float4* vp = (const float4*)(qkvs + (size_t)s * QKVS_W + 512);
        float4 k0 = __ldg(&kp[lane * 2]), k1 = __ldg(&kp[lane * 2 + 1]);
        float4 v0 = __ldg(&vp[lane * 2]), v1 = __ldg(&vp[lane * 2 + 1]);
        float p = q0.x * k0.x + q0.y * k0.y + q0.z * k0.z + q0.w * k0.w
                + q1.x * k1.x + q1.y * k1.y + q1.z * k1.z + q1.w * k1.w;
        p += __shfl_xor_sync(0xffffffffu, p, 1);
        p += __shfl_xor_sync(0xffffffffu, p, 2);
        p += __shfl_xor_sync(0xffffffffu, p, 4);
        float ex = __expf(p * 0.125f);
        dsum += ex;
        a0x += v0.x * ex; a0y += v0.y * ex; a0z += v0.z * ex; a0w += v0.w * ex;
        a1x += v1.x * ex; a1y += v1.y * ex; a1z += v1.z * ex; a1w += v1.w * ex;
    }

    float inv = (dsum > 0.f) ? (1.0f / dsum) : 0.f;
    const float4* sp = (const float4*)(qkvs + (size_t)warp * QKVS_W + 768);
    float4 s0 = __ldg(&sp[lane * 2]), s1 = __ldg(&sp[lane * 2 + 1]);
    float4 o0 = make_float4(a0x * inv + s0.x, a0y * inv + s0.y,
                            a0z * inv + s0.z, a0w * inv + s0.w);
    float4 o1 = make_float4(a1x * inv + s1.x, a1y * inv + s1.y,
                            a1z * inv + s1.z, a1w * inv + s1.w);
    float4* op = (float4*)(accum + (size_t)warp * WIDTH + lane * 8);
    op[0] = o0;
    op[1] = o1;
}

// ================= BN stats ==================================================
#define FIN_ROWS 32
__global__ void __launch_bounds__(256) stats_kernel(
    const float* __restrict__ accum, float* __restrict__ stats, int M)
{
    const int c = threadIdx.x;
    const int r0 = blockIdx.x * FIN_ROWS;
    float s1 = 0.f, s2 = 0.f;
#pragma unroll 4
    for (int r = 0; r < FIN_ROWS; r++) {
        int n = r0 + r;
        if (n >= M) break;
        float v = accum[(size_t)n * WIDTH + c];
        s1 += v; s2 += v * v;
    }
    atomicAdd(&stats[c], s1);
    atomicAdd(&stats[WIDTH + c], s2);
}

__global__ void __launch_bounds__(256) bn_act(
    const float* __restrict__ in, const float* __restrict__ stats,
    const float* __restrict__ gamma, const float* __restrict__ beta,
    float* __restrict__ out, int M, float invN)
{
    int idx = blockIdx.x * blockDim.x + threadIdx.x;
    int total = M * WIDTH;
    int stride = gridDim.x * blockDim.x;
    for (; idx < total; idx += stride) {
        int c = idx & (WIDTH - 1);
        float mean = stats[c] * invN;
        float var  = stats[WIDTH + c] * invN - mean * mean;
        float sc = rsqrtf(var + 1e-5f) * gamma[c];
        float sh = beta[c] - mean * sc;
        float v = in[idx] * sc + sh;
        out[idx] = (v >= 0.f) ? v : 0.1f * v;
    }
}

// BN + leaky-relu + bf16 hi/lo split, feeding the next GEMM directly
__global__ void __launch_bounds__(256) bn_act_split(
    const float* __restrict__ in, const float* __restrict__ stats,
    const float* __restrict__ gamma, const float* __restrict__ beta,
    __nv_bfloat16* __restrict__ hi, __nv_bfloat16* __restrict__ lo,
    int n4, float invN)
{
    int i = blockIdx.x * blockDim.x + threadIdx.x;
    int stride = gridDim.x * blockDim.x;
    for (; i < n4; i += stride) {
        int c = (i & 63) * 4;
        float4 v = ((const float4*)in)[i];
        float r[4] = {v.x, v.y, v.z, v.w};
        __nv_bfloat16 hh[4], ll[4];
#pragma unroll
        for (int j = 0; j < 4; j++) {
            int cc = c + j;
            float mean = stats[cc] * invN;
            float var  = stats[WIDTH + cc] * invN - mean * mean;
            float sc = rsqrtf(var + 1e-5f) * gamma[cc];
            float sh = beta[cc] - mean * sc;
            float x = r[j] * sc + sh;
            x = (x >= 0.f) ? x : 0.1f * x;
            hh[j] = __float2bfloat16(x);
            ll[j] = __float2bfloat16(x - __bfloat162float(hh[j]));
        }
        ((__nv_bfloat162*)hi)[i * 2]     = __nv_bfloat162(hh[0], hh[1]);
        ((__nv_bfloat162*)hi)[i * 2 + 1] = __nv_bfloat162(hh[2], hh[3]);
        ((__nv_bfloat162*)lo)[i * 2]     = __nv_bfloat162(ll[0], ll[1]);
        ((__nv_bfloat162*)lo)[i * 2 + 1] = __nv_bfloat162(ll[2], ll[3]);
    }
}

// ================= launch ====================================================
extern "C" void kernel_launch(void* const* d_in, const int* in_sizes, int n_in,
                              void* d_out, int out_size)
{
    const float* x  = (const float*)d_in[0];
    const void*  ei = d_in[1];
    WPtrs wp;
    for (int i = 0; i < 4; i++) {
        wp.w[i]     = (const float*)d_in[2 + i * 2];
        wp.b[i]     = (const float*)d_in[3 + i * 2];
        wp.w[4 + i] = (const float*)d_in[12 + i * 2];
        wp.b[4 + i] = (const float*)d_in[13 + i * 2];
    }
    const float* g1  = (const float*)d_in[10]; const float* be1 = (const float*)d_in[11];
    const float* g2  = (const float*)d_in[20]; const float* be2 = (const float*)d_in[21];

    const int M = in_sizes[0] / WIDTH;   // 30000
    const int E = in_sizes[1] / 2;       // 600000

    float *qkvs, *accum, *stats, *biasc;
    __nv_bfloat16 *ahi, *alo, *bthi, *btlo;
    int *deg, *off, *pos, *csr;
    cudaGetSymbolAddress((void**)&qkvs,  g_qkvs);
    cudaGetSymbolAddress((void**)&accum, g_accum);
    cudaGetSymbolAddress((void**)&stats, g_stats);
    cudaGetSymbolAddress((void**)&ahi,   g_ahi);
    cudaGetSymbolAddress((void**)&alo,   g_alo);
    cudaGetSymbolAddress((void**)&bthi,  g_bthi);
    cudaGetSymbolAddress((void**)&btlo,  g_btlo);
    cudaGetSymbolAddress((void**)&biasc, g_biasc);
    cudaGetSymbolAddress((void**)&deg,   g_deg);
    cudaGetSymbolAddress((void**)&off,   g_off);
    cudaGetSymbolAddress((void**)&pos,   g_pos);
    cudaGetSymbolAddress((void**)&csr,   g_csr);

    cudaFuncSetAttribute(gemm_mma, cudaFuncAttributeMaxDynamicSharedMemorySize, SM_BYTES);

    dim3 ggrid(16, (M + 127) / 128);
    int eb = (E + 255) / 256;
    int agg_blocks  = (M * 32 + 255) / 256;
    int stat_blocks = (M + FIN_ROWS - 1) / FIN_ROWS;
    float invN = 1.0f / (float)M;

    // ---- prep (once, single stream) ----
    detect_idx_kernel<<<1, 512>>>((const int*)ei, 2 * E);
    prep_weights<<<dim3(8, 8, 8), dim3(32, 8)>>>(wp, bthi, btlo);
    prep_bias<<<8, 256>>>(wp, biasc);

    // ---- CSR build (once) ----
    cudaMemsetAsync(deg, 0, M * sizeof(int));
    hist_kernel<<<eb, 256>>>(ei, deg, E, M);
    scan_kernel<<<1, 1024>>>(deg, off, pos, M);
    scatter_kernel<<<eb, 256>>>(ei, pos, csr, E, M);

    // ---- layer 1 ----
    split_a_kernel<<<960, 512>>>(x, ahi, alo, M * 64);
    gemm_mma<<<ggrid, GTHREADS, SM_BYTES>>>(ahi, alo, bthi, btlo, biasc, qkvs, M);
    edge_agg<<<agg_blocks, 256>>>(qkvs, off, csr, accum, M);
    cudaMemsetAsync(stats, 0, 2 * WIDTH * sizeof(float));
    stats_kernel<<<stat_blocks, 256>>>(accum, stats, M);
    bn_act_split<<<480, 256>>>(accum, stats, g1, be1, ahi, alo, M * 64, invN);

    // ---- layer 2 ----
    gemm_mma<<<ggrid, GTHREADS, SM_BYTES>>>(ahi, alo, bthi + (size_t)1024 * 256,
                                            btlo + (size_t)1024 * 256, biasc + 1024, qkvs, M);
    edge_agg<<<agg_blocks, 256>>>(qkvs, off, csr, accum, M);
    cudaMemsetAsync(stats, 0, 2 * WIDTH * sizeof(float));
    stats_kernel<<<stat_blocks, 256>>>(accum, stats, M);
    bn_act<<<480, 256>>>(accum, stats, g2, be2, (float*)d_out, M, invN);
}

// round 16
// speedup vs baseline: 1.7502x; 1.1389x over previous
#include <cuda_runtime.h>
#include <cuda_bf16.h>
#include <cuda_fp16.h>
#include <cstdint>
#include <cstddef>

// Problem constants (fixed by reference)
#define NNODES 30000
#define EMAX   600000
#define WIDTH  256      // heads(4) * per-head(64)

// ================= scratch (static device globals; no allocation) ===========
__device__ __align__(16) float  g_qs [(size_t)NNODES * 512];   // q | skip (fp32)
__device__ __align__(16) __half g_kv [(size_t)NNODES * 512];   // k | v (fp16)
__device__ __align__(16) float  g_accum[(size_t)NNODES * WIDTH];
__device__ __align__(16) float  g_stats[2 * WIDTH];            // sum | sumsq
__device__ int g_is64;

// CSR scratch (built once per launch; reused by both layers)
__device__ int g_deg[NNODES];
__device__ int g_off[NNODES + 1];
__device__ int g_pos[NNODES];
__device__ int g_csr[EMAX];

// bf16 split-precision scratch
__device__ __align__(16) __nv_bfloat16 g_ahi [(size_t)NNODES * 256];
__device__ __align__(16) __nv_bfloat16 g_alo [(size_t)NNODES * 256];
__device__ __align__(16) __nv_bfloat16 g_bthi[2u * 1024 * 256];   // Bt[n][k] per layer
__device__ __align__(16) __nv_bfloat16 g_btlo[2u * 1024 * 256];
__device__ __align__(16) float         g_biasc[2 * 1024];

// ================= small kernels =============================================
__global__ void __launch_bounds__(512) detect_idx_kernel(
    const int* __restrict__ ei32, int nwords) {
    __shared__ int bad;
    if (threadIdx.x == 0) bad = 0;
    __syncthreads();
    int lim = nwords < 4096 ? nwords : 4096;
    int nz = 0;
    for (int i = 1 + 2 * threadIdx.x; i < lim; i += 2 * 512)
        nz |= (ei32[i] != 0);
    if (nz) atomicOr(&bad, 1);
    __syncthreads();
    if (threadIdx.x == 0) g_is64 = !bad;
}

__device__ __forceinline__ int load_idx(const void* ei, int i) {
    if (g_is64) return (int)((const long long*)ei)[i];
    return ((const int*)ei)[i];
}

__global__ void hist_kernel(const void* __restrict__ ei, int* __restrict__ deg,
                            int E, int M) {
    int e = blockIdx.x * blockDim.x + threadIdx.x;
    if (e >= E) return;
    int dst = load_idx(ei, E + e);
    if ((unsigned)dst < (unsigned)M) atomicAdd(&deg[dst], 1);
}

__global__ void __launch_bounds__(1024) scan_kernel(
    const int* __restrict__ deg, int* __restrict__ off, int* __restrict__ pos, int n) {
    __shared__ int s[1024];
    int t = threadIdx.x;
    int chunk = (n + 1023) / 1024;
    int base = t * chunk;
    int sum = 0;
    for (int i = 0; i < chunk; i++) {
        int idx = base + i;
        if (idx < n) sum += deg[idx];
    }
    s[t] = sum;
    __syncthreads();
    for (int d = 1; d < 1024; d <<= 1) {
        int u = (t >= d) ? s[t - d] : 0;
        __syncthreads();
        s[t] += u;
        __syncthreads();
    }
    int run = s[t] - sum;
    for (int i = 0; i < chunk; i++) {
        int idx = base + i;
        if (idx < n) {
            off[idx] = run;
            pos[idx] = run;
            run += deg[idx];
        }
    }
    if (t == 1023) off[n] = s[1023];
}

__global__ void scatter_kernel(const void* __restrict__ ei, int* __restrict__ pos,
                               int* __restrict__ csr, int E, int M) {
    int e = blockIdx.x * blockDim.x + threadIdx.x;
    if (e >= E) return;
    int src = load_idx(ei, e);
    int dst = load_idx(ei, E + e);
    if ((unsigned)dst >= (unsigned)M || (unsigned)src >= (unsigned)M) return;
    int p = atomicAdd(&pos[dst], 1);
    csr[p] = src;
}

// split fp32 -> bf16 hi/lo (4 elems/thread)
__global__ void split_a_kernel(const float* __restrict__ src,
                               __nv_bfloat16* __restrict__ hi,
                               __nv_bfloat16* __restrict__ lo, int n4) {
    int i = blockIdx.x * blockDim.x + threadIdx.x;
    int s = gridDim.x * blockDim.x;
    for (; i < n4; i += s) {
        float4 v = ((const float4*)src)[i];
        __nv_bfloat16 h0 = __float2bfloat16(v.x), h1 = __float2bfloat16(v.y);
        __nv_bfloat16 h2 = __float2bfloat16(v.z), h3 = __float2bfloat16(v.w);
        __nv_bfloat16 l0 = __float2bfloat16(v.x - __bfloat162float(h0));
        __nv_bfloat16 l1 = __float2bfloat16(v.y - __bfloat162float(h1));
        __nv_bfloat16 l2 = __float2bfloat16(v.z - __bfloat162float(h2));
        __nv_bfloat16 l3 = __float2bfloat16(v.w - __bfloat162float(h3));
        ((__nv_bfloat162*)hi)[i * 2]     = __nv_bfloat162(h0, h1);
        ((__nv_bfloat162*)hi)[i * 2 + 1] = __nv_bfloat162(h2, h3);
        ((__nv_bfloat162*)lo)[i * 2]     = __nv_bfloat162(l0, l1);
        ((__nv_bfloat162*)lo)[i * 2 + 1] = __nv_bfloat162(l2, l3);
    }
}

struct WPtrs { const float* w[8]; const float* b[8]; };

__global__ void prep_weights(WPtrs P, __nv_bfloat16* __restrict__ bthi,
                             __nv_bfloat16* __restrict__ btlo) {
    const float* W = P.w[blockIdx.z];
    int layer = blockIdx.z >> 2, j = blockIdx.z & 3;
    __shared__ float t[32][33];
    int tx = threadIdx.x, ty = threadIdx.y;
    int c0 = blockIdx.x * 32, k0 = blockIdx.y * 32;
#pragma unroll
    for (int r = 0; r < 4; r++) {
        int k = k0 + ty + r * 8;
        t[ty + r * 8][tx] = W[k * 256 + c0 + tx];
    }
    __syncthreads();
#pragma unroll
    for (int r = 0; r < 4; r++) {
        int c = c0 + ty + r * 8;
        int k = k0 + tx;
        float v = t[tx][ty + r * 8];
        __nv_bfloat16 h = __float2bfloat16(v);
        size_t o = ((size_t)layer * 1024 + j * 256 + c) * 256 + k;
        bthi[o] = h;
        btlo[o] = __float2bfloat16(v - __bfloat162float(h));
    }
}

__global__ void prep_bias(WPtrs P, float* __restrict__ biasc) {
    int idx = blockIdx.x * blockDim.x + threadIdx.x;
    if (idx < 2048) {
        int layer = idx >> 10, j = (idx >> 8) & 3, c = idx & 255;
        biasc[idx] = P.b[layer * 4 + j][c];
    }
}

// == mma.sync bf16 GEMM, 2-stage cp.async, CTA 128x64, 4 warps (2x2), 2 CTA/SM =
// Epilogue: q/s segments -> fp32 g_qs, k/v segments -> fp16 g_kv (uniform per CTA)
#define KPAD 72
#define A_TILE_B (128 * KPAD)
#define B_TILE_B (64 * KPAD)
#define STAGE_B (2 * A_TILE_B + 2 * B_TILE_B)
#define SM_BYTES (2 * STAGE_B * 2)
#define GTHREADS 128

__device__ __forceinline__ void mma16816(float* d, const uint32_t* a,
                                          const uint32_t* b) {
    asm volatile(
        "mma.sync.aligned.m16n8k16.row.col.f32.bf16.bf16.f32 "
        "{%0,%1,%2,%3}, {%4,%5,%6,%7}, {%8,%9}, {%0,%1,%2,%3};"
        : "+f"(d[0]), "+f"(d[1]), "+f"(d[2]), "+f"(d[3])
        : "r"(a[0]), "r"(a[1]), "r"(a[2]), "r"(a[3]), "r"(b[0]), "r"(b[1]));
}

__device__ __forceinline__ void cpa16(uint32_t dst_s, const void* src, bool valid) {
    int sz = valid ? 16 : 0;
    asm volatile("cp.async.cg.shared.global [%0], [%1], 16, %2;"
                 :: "r"(dst_s), "l"(src), "r"(sz));
}

__device__ __forceinline__ void load_tile_a(
    uint32_t s, const __nv_bfloat16* __restrict__ g,
    int row0, int rowlim, int k0, int tid) {
#pragma unroll
    for (int it = 0; it < 8; it++) {
        int idx = it * GTHREADS + tid;
        int row = idx >> 3;
        int c8  = (idx & 7) * 8;
        int r = row0 + row;
        cpa16(s + (row * KPAD + c8) * 2, g + (size_t)r * 256 + k0 + c8, r < rowlim);
    }
}

__device__ __forceinline__ void load_tile_b(
    uint32_t s, const __nv_bfloat16* __restrict__ g, int k0, int tid) {
#pragma unroll
    for (int it = 0; it < 4; it++) {
        int idx = it * GTHREADS + tid;
        int row = idx >> 3;
        int c8  = (idx & 7) * 8;
        cpa16(s + (row * KPAD + c8) * 2, g + (size_t)row * 256 + k0 + c8, true);
    }
}

__device__ __forceinline__ void issue_stage(
    uint32_t sb, int stage,
    const __nv_bfloat16* ahi, const __nv_bfloat16* alo,
    const __nv_bfloat16* bh, const __nv_bfloat16* bl,
    int m0, int M, int k0, int tid) {
    uint32_t s = sb + stage * STAGE_B * 2;
    load_tile_a(s,                               ahi, m0, M, k0, tid);
    load_tile_a(s + A_TILE_B * 2,                alo, m0, M, k0, tid);
    load_tile_b(s + A_TILE_B * 4,                bh, k0, tid);
    load_tile_b(s + A_TILE_B * 4 + B_TILE_B * 2, bl, k0, tid);
    asm volatile("cp.async.commit_group;");
}

__global__ void __launch_bounds__(GTHREADS, 2) gemm_mma(
    const __nv_bfloat16* __restrict__ ahi, const __nv_bfloat16* __restrict__ alo,
    const __nv_bfloat16* __restrict__ bthi, const __nv_bfloat16* __restrict__ btlo,
    const float* __restrict__ bias,
    float* __restrict__ qs_out, __half* __restrict__ kv_out, int M)
{
    extern __shared__ __align__(16) __nv_bfloat16 sm[];
    uint32_t sb = (uint32_t)__cvta_generic_to_shared(sm);

    const int tid = threadIdx.x;
    const int wid = tid >> 5, lane = tid & 31;
    const int wm = wid & 1, wn = wid >> 1;     // 2x2 warp grid
    const int g = lane >> 2, t = lane & 3;
    const int nt = blockIdx.x;                 // 0..15 : 64-col block
    const int m0 = blockIdx.y * 128;

    const __nv_bfloat16* bh = bthi + (size_t)nt * 64 * 256;
    const __nv_bfloat16* bl = btlo + (size_t)nt * 64 * 256;

    float acc[4][4][4];
#pragma unroll
    for (int i = 0; i < 4; i++)
#pragma unroll
        for (int j = 0; j < 4; j++)
#pragma unroll
            for (int k = 0; k < 4; k++) acc[i][j][k] = 0.f;

    issue_stage(sb, 0, ahi, alo, bh, bl, m0, M, 0, tid);

    for (int kc = 0; kc < 4; kc++) {
        if (kc + 1 < 4) {
            issue_stage(sb, (kc + 1) & 1, ahi, alo, bh, bl, m0, M, (kc + 1) * 64, tid);
            asm volatile("cp.async.wait_group 1;");
        } else {
            asm volatile("cp.async.wait_group 0;");
        }
        __syncthreads();

        const __nv_bfloat16* sAh = sm + (kc & 1) * STAGE_B;
        const __nv_bfloat16* sAl = sAh + A_TILE_B;
        const __nv_bfloat16* sBh = sAh + 2 * A_TILE_B;
        const __nv_bfloat16* sBl = sBh + B_TILE_B;

#pragma unroll
        for (int ks = 0; ks < 4; ks++) {
            const int kb = ks * 16 + t * 2;
            uint32_t a_h[4][4], a_l[4][4];
#pragma unroll
            for (int mf = 0; mf < 4; mf++) {
                int r = wm * 64 + mf * 16 + g;
                a_h[mf][0] = *(const uint32_t*)(sAh + r * KPAD + kb);
                a_h[mf][1] = *(const uint32_t*)(sAh + (r + 8) * KPAD + kb);
                a_h[mf][2] = *(const uint32_t*)(sAh + r * KPAD + kb + 8);
                a_h[mf][3] = *(const uint32_t*)(sAh + (r + 8) * KPAD + kb + 8);
                a_l[mf][0] = *(const uint32_t*)(sAl + r * KPAD + kb);
                a_l[mf][1] = *(const uint32_t*)(sAl + (r + 8) * KPAD + kb);
                a_l[mf][2] = *(const uint32_t*)(sAl + r * KPAD + kb + 8);
                a_l[mf][3] = *(const uint32_t*)(sAl + (r + 8) * KPAD + kb + 8);
            }
#pragma unroll
            for (int nf = 0; nf < 4; nf++) {
                int c = wn * 32 + nf * 8 + g;
                uint32_t b_h[2], b_l[2];
                b_h[0] = *(const uint32_t*)(sBh + c * KPAD + kb);
                b_h[1] = *(const uint32_t*)(sBh + c * KPAD + kb + 8);
                b_l[0] = *(const uint32_t*)(sBl + c * KPAD + kb);
                b_l[1] = *(const uint32_t*)(sBl + c * KPAD + kb + 8);
#pragma unroll
                for (int mf = 0; mf < 4; mf++) {
                    mma16816(acc[mf][nf], a_h[mf], b_h);
                    mma16816(acc[mf][nf], a_h[mf], b_l);
                    mma16816(acc[mf][nf], a_l[mf], b_h);
                }
            }
        }
        __syncthreads();
    }

    // epilogue: nt 0-3 -> q (fp32), nt 4-11 -> k|v (fp16), nt 12-15 -> s (fp32)
    const bool is_kv = (nt >= 4) && (nt < 12);
#pragma unroll
    for (int mf = 0; mf < 4; mf++) {
        int r0 = m0 + wm * 64 + mf * 16 + g;
#pragma unroll
        for (int nf = 0; nf < 4; nf++) {
            int cg = nt * 64 + wn * 32 + nf * 8 + t * 2;
            float bx = bias[cg], by = bias[cg + 1];
            float v0x = acc[mf][nf][0] + bx, v0y = acc[mf][nf][1] + by;
            float v1x = acc[mf][nf][2] + bx, v1y = acc[mf][nf][3] + by;
            if (is_kv) {
                int kc2 = cg - 256;     // 0..511 within kv buffer
                if (r0 < M)
                    *(__half2*)(kv_out + (size_t)r0 * 512 + kc2) = __floats2half2_rn(v0x, v0y);
                if (r0 + 8 < M)
                    *(__half2*)(kv_out + (size_t)(r0 + 8) * 512 + kc2) = __floats2half2_rn(v1x, v1y);
            } else {
                int qc = (nt < 4) ? cg : cg - 512;   // 0..511 within qs buffer
                if (r0 < M)
                    *(float2*)(qs_out + (size_t)r0 * 512 + qc) = make_float2(v0x, v0y);
                if (r0 + 8 < M)
                    *(float2*)(qs_out + (size_t)(r0 + 8) * 512 + qc) = make_float2(v1x, v1y);
            }
        }
    }
}

// ======= gather edge aggregation (2-edge unroll, fp16 k/v, barrier-free) ====
__device__ __forceinline__ float dot8h(const uint4& k, const float4& q0, const float4& q1) {
    const __half2* h = (const __half2*)&k;
    float2 f0 = __half22float2(h[0]);
    float2 f1 = __half22float2(h[1]);
    float2 f2 = __half22float2(h[2]);
    float2 f3 = __half22float2(h[3]);
    return q0.x * f0.x + q0.y * f0.y + q0.z * f1.x + q0.w * f1.y
         + q1.x * f2.x + q1.y * f2.y + q1.z * f3.x + q1.w * f3.y;
}

__device__ __forceinline__ void acc8h(const uint4& v, float ex,
                                      float* a0, float* a1) {
    const __half2* h = (const __half2*)&v;
    float2 f0 = __half22float2(h[0]);
    float2 f1 = __half22float2(h[1]);
    float2 f2 = __half22float2(h[2]);
    float2 f3 = __half22float2(h[3]);
    a0[0] += f0.x * ex; a0[1] += f0.y * ex; a0[2] += f1.x * ex; a0[3] += f1.y * ex;
    a1[0] += f2.x * ex; a1[1] += f2.y * ex; a1[2] += f3.x * ex; a1[3] += f3.y * ex;
}

__global__ void __launch_bounds__(256) edge_agg(
    const float* __restrict__ qs, const __half* __restrict__ kv,
    const int* __restrict__ off, const int* __restrict__ csr,
    float* __restrict__ accum, int M)
{
    int warp = (blockIdx.x * blockDim.x + threadIdx.x) >> 5;
    int lane = threadIdx.x & 31;
    if (warp >= M) return;

    const float4* qp = (const float4*)(qs + (size_t)warp * 512);
    float4 q0 = __ldg(&qp[lane * 2]), q1 = __ldg(&qp[lane * 2 + 1]);

    int i0 = off[warp], i1 = off[warp + 1];
    float a0[4] = {0.f, 0.f, 0.f, 0.f};
    float a1[4] = {0.f, 0.f, 0.f, 0.f};
    float dsum = 0.f;

    int i = i0;
    for (; i + 2 <= i1; i += 2) {
        int sa = __ldg(&csr[i]), sb = __ldg(&csr[i + 1]);
        const __half* pa = kv + (size_t)sa * 512 + lane * 8;
        const __half* pb = kv + (size_t)sb * 512 + lane * 8;
        uint4 ka = __ldg((const uint4*)pa);
        uint4 kb = __ldg((const uint4*)pb);
        uint4 va = __ldg((const uint4*)(pa + 256));
        uint4 vb = __ldg((const uint4*)(pb + 256));

        float p_a = dot8h(ka, q0, q1);
        float p_b = dot8h(kb, q0, q1);
        p_a += __shfl_xor_sync(0xffffffffu, p_a, 1);
        p_b += __shfl_xor_sync(0xffffffffu, p_b, 1);
        p_a += __shfl_xor_sync(0xffffffffu, p_a, 2);
        p_b += __shfl_xor_sync(0xffffffffu, p_b, 2);
        p_a += __shfl_xor_sync(0xffffffffu, p_a, 4);
        p_b += __shfl_xor_sync(0xffffffffu, p_b, 4);
        float exa = __expf(p_a * 0.125f);
        float exb = __expf(p_b * 0.125f);
        dsum += exa + exb;
        acc8h(va, exa, a0, a1);
        acc8h(vb, exb, a0, a1);
    }
    if (i < i1) {
        int s = __ldg(&csr[i]);
        const __half* pk = kv + (size_t)s * 512 + lane * 8;
        uint4 k = __ldg((const uint4*)pk);
        uint4 v = __ldg((const uint4*)(pk + 256));
        float p = dot8h(k, q0, q1);
        p += __shfl_xor_sync(0xffffffffu, p, 1);
        p += __shfl_xor_sync(0xffffffffu, p, 2);
        p += __shfl_xor_sync(0xffffffffu, p, 4);
        float ex = __expf(p * 0.125f);
        dsum += ex;
        acc8h(v, ex, a0, a1);
    }

    float inv = (dsum > 0.f) ? (1.0f / dsum) : 0.f;
    const float4* sp = (const float4*)(qs + (size_t)warp * 512 + 256);
    float4 s0 = __ldg(&sp[lane * 2]), s1 = __ldg(&sp[lane * 2 + 1]);
    float4 o0 = make_float4(a0[0] * inv + s0.x, a0[1] * inv + s0.y,
                            a0[2] * inv + s0.z, a0[3] * inv + s0.w);
    float4 o1 = make_float4(a1[0] * inv + s1.x, a1[1] * inv + s1.y,
                            a1[2] * inv + s1.z, a1[3] * inv + s1.w);
    float4* op = (float4*)(accum + (size_t)warp * WIDTH + lane * 8);
    op[0] = o0;
    op[1] = o1;
}

// ================= BN stats ==================================================
#define FIN_ROWS 32
__global__ void __launch_bounds__(256) stats_kernel(
    const float* __restrict__ accum, float* __restrict__ stats, int M)
{
    const int c = threadIdx.x;
    const int r0 = blockIdx.x * FIN_ROWS;
    float s1 = 0.f, s2 = 0.f;
#pragma unroll 4
    for (int r = 0; r < FIN_ROWS; r++) {
        int n = r0 + r;
        if (n >= M) break;
        float v = accum[(size_t)n * WIDTH + c];
        s1 += v; s2 += v * v;
    }
    atomicAdd(&stats[c], s1);
    atomicAdd(&stats[WIDTH + c], s2);
}

__global__ void __launch_bounds__(256) bn_act(
    const float* __restrict__ in, const float* __restrict__ stats,
    const float* __restrict__ gamma, const float* __restrict__ beta,
    float* __restrict__ out, int M, float invN)
{
    int idx = blockIdx.x * blockDim.x + threadIdx.x;
    int total = M * WIDTH;
    int stride = gridDim.x * blockDim.x;
    for (; idx < total; idx += stride) {
        int c = idx & (WIDTH - 1);
        float mean = stats[c] * invN;
        float var  = stats[WIDTH + c] * invN - mean * mean;
        float sc = rsqrtf(var + 1e-5f) * gamma[c];
        float sh = beta[c] - mean * sc;
        float v = in[idx] * sc + sh;
        out[idx] = (v >= 0.f) ? v : 0.1f * v;
    }
}

// BN + leaky-relu + bf16 hi/lo split, feeding the next GEMM directly
__global__ void __launch_bounds__(256) bn_act_split(
    const float* __restrict__ in, const float* __restrict__ stats,
    const float* __restrict__ gamma, const float* __restrict__ beta,
    __nv_bfloat16* __restrict__ hi, __nv_bfloat16* __restrict__ lo,
    int n4, float invN)
{
    int i = blockIdx.x * blockDim.x + threadIdx.x;
    int stride = gridDim.x * blockDim.x;
    for (; i < n4; i += stride) {
        int c = (i & 63) * 4;
        float4 v = ((const float4*)in)[i];
        float r[4] = {v.x, v.y, v.z, v.w};
        __nv_bfloat16 hh[4], ll[4];
#pragma unroll
        for (int j = 0; j < 4; j++) {
            int cc = c + j;
            float mean = stats[cc] * invN;
            float var  = stats[WIDTH + cc] * invN - mean * mean;
            float sc = rsqrtf(var + 1e-5f) * gamma[cc];
            float sh = beta[cc] - mean * sc;
            float x = r[j] * sc + sh;
            x = (x >= 0.f) ? x : 0.1f * x;
            hh[j] = __float2bfloat16(x);
            ll[j] = __float2bfloat16(x - __bfloat162float(hh[j]));
        }
        ((__nv_bfloat162*)hi)[i * 2]     = __nv_bfloat162(hh[0], hh[1]);
        ((__nv_bfloat162*)hi)[i * 2 + 1] = __nv_bfloat162(hh[2], hh[3]);
        ((__nv_bfloat162*)lo)[i * 2]     = __nv_bfloat162(ll[0], ll[1]);
        ((__nv_bfloat162*)lo)[i * 2 + 1] = __nv_bfloat162(ll[2], ll[3]);
    }
}

// ================= launch ====================================================
extern "C" void kernel_launch(void* const* d_in, const int* in_sizes, int n_in,
                              void* d_out, int out_size)
{
    const float* x  = (const float*)d_in[0];
    const void*  ei = d_in[1];
    WPtrs wp;
    for (int i = 0; i < 4; i++) {
        wp.w[i]     = (const float*)d_in[2 + i * 2];
        wp.b[i]     = (const float*)d_in[3 + i * 2];
        wp.w[4 + i] = (const float*)d_in[12 + i * 2];
        wp.b[4 + i] = (const float*)d_in[13 + i * 2];
    }
    const float* g1  = (const float*)d_in[10]; const float* be1 = (const float*)d_in[11];
    const float* g2  = (const float*)d_in[20]; const float* be2 = (const float*)d_in[21];

    const int M = in_sizes[0] / WIDTH;   // 30000
    const int E = in_sizes[1] / 2;       // 600000

    float *qs, *accum, *stats, *biasc;
    __half *kv;
    __nv_bfloat16 *ahi, *alo, *bthi, *btlo;
    int *deg, *off, *pos, *csr;
    cudaGetSymbolAddress((void**)&qs,    g_qs);
    cudaGetSymbolAddress((void**)&kv,    g_kv);
    cudaGetSymbolAddress((void**)&accum, g_accum);
    cudaGetSymbolAddress((void**)&stats, g_stats);
    cudaGetSymbolAddress((void**)&ahi,   g_ahi);
    cudaGetSymbolAddress((void**)&alo,   g_alo);
    cudaGetSymbolAddress((void**)&bthi,  g_bthi);
    cudaGetSymbolAddress((void**)&btlo,  g_btlo);
    cudaGetSymbolAddress((void**)&biasc, g_biasc);
    cudaGetSymbolAddress((void**)&deg,   g_deg);
    cudaGetSymbolAddress((void**)&off,   g_off);
    cudaGetSymbolAddress((void**)&pos,   g_pos);
    cudaGetSymbolAddress((void**)&csr,   g_csr);

    cudaFuncSetAttribute(gemm_mma, cudaFuncAttributeMaxDynamicSharedMemorySize, SM_BYTES);

    dim3 ggrid(16, (M + 127) / 128);
    int eb = (E + 255) / 256;
    int agg_blocks  = (M * 32 + 255) / 256;
    int stat_blocks = (M + FIN_ROWS - 1) / FIN_ROWS;
    float invN = 1.0f / (float)M;

    // ---- prep (once, single stream) ----
    detect_idx_kernel<<<1, 512>>>((const int*)ei, 2 * E);
    prep_weights<<<dim3(8, 8, 8), dim3(32, 8)>>>(wp, bthi, btlo);
    prep_bias<<<8, 256>>>(wp, biasc);

    // ---- CSR build (once) ----
    cudaMemsetAsync(deg, 0, M * sizeof(int));
    hist_kernel<<<eb, 256>>>(ei, deg, E, M);
    scan_kernel<<<1, 1024>>>(deg, off, pos, M);
    scatter_kernel<<<eb, 256>>>(ei, pos, csr, E, M);

    // ---- layer 1 ----
    split_a_kernel<<<960, 512>>>(x, ahi, alo, M * 64);
    gemm_mma<<<ggrid, GTHREADS, SM_BYTES>>>(ahi, alo, bthi, btlo, biasc, qs, kv, M);
    edge_agg<<<agg_blocks, 256>>>(qs, kv, off, csr, accum, M);
    cudaMemsetAsync(stats, 0, 2 * WIDTH * sizeof(float));
    stats_kernel<<<stat_blocks, 256>>>(accum, stats, M);
    bn_act_split<<<480, 256>>>(accum, stats, g1, be1, ahi, alo, M * 64, invN);

    // ---- layer 2 ----
    gemm_mma<<<ggrid, GTHREADS, SM_BYTES>>>(ahi, alo, bthi + (size_t)1024 * 256,
                                            btlo + (size_t)1024 * 256, biasc + 1024, qs, kv, M);
    edge_agg<<<agg_blocks, 256>>>(qs, kv, off, csr, accum, M);
    cudaMemsetAsync(stats, 0, 2 * WIDTH * sizeof(float));
    stats_kernel<<<stat_blocks, 256>>>(accum, stats, M);
    bn_act<<<480, 256>>>(accum, stats, g2, be2, (float*)d_out, M, invN);
}

// round 17
// speedup vs baseline: 2.0071x; 1.1468x over previous
#include <cuda_runtime.h>
#include <cuda_fp16.h>
#include <cstdint>
#include <cstddef>

// Problem constants (fixed by reference)
#define NNODES 30000
#define EMAX   600000
#define WIDTH  256      // heads(4) * per-head(64)

// ================= scratch (static device globals; no allocation) ===========
__device__ __align__(16) float  g_qs [(size_t)NNODES * 512];   // q | skip (fp32)
__device__ __align__(16) __half g_kv [(size_t)NNODES * 512];   // k | v (fp16)
__device__ __align__(16) float  g_accum[(size_t)NNODES * WIDTH];
__device__ __align__(16) float  g_stats[4 * WIDTH];            // layer1: sum|sq, layer2: sum|sq
__device__ int g_is64;

// CSR scratch (built once per launch; reused by both layers)
__device__ int g_deg[NNODES];
__device__ int g_off[NNODES + 1];
__device__ int g_pos[NNODES];
__device__ int g_csr[EMAX];

// fp16 split-precision scratch
__device__ __align__(16) __half g_ahi [(size_t)NNODES * 256];
__device__ __align__(16) __half g_alo [(size_t)NNODES * 256];
__device__ __align__(16) __half g_btf [2u * 1024 * 256];       // Bt[n][k] fp16, per layer
__device__ __align__(16) float  g_biasc[2 * 1024];

// ================= small kernels =============================================
__global__ void __launch_bounds__(512) detect_idx_kernel(
    const int* __restrict__ ei32, int nwords) {
    __shared__ int bad;
    if (threadIdx.x == 0) bad = 0;
    __syncthreads();
    int lim = nwords < 4096 ? nwords : 4096;
    int nz = 0;
    for (int i = 1 + 2 * threadIdx.x; i < lim; i += 2 * 512)
        nz |= (ei32[i] != 0);
    if (nz) atomicOr(&bad, 1);
    __syncthreads();
    if (threadIdx.x == 0) g_is64 = !bad;
}

__device__ __forceinline__ int load_idx(const void* ei, int i) {
    if (g_is64) return (int)((const long long*)ei)[i];
    return ((const int*)ei)[i];
}

__global__ void hist_kernel(const void* __restrict__ ei, int* __restrict__ deg,
                            int E, int M) {
    int e = blockIdx.x * blockDim.x + threadIdx.x;
    if (e >= E) return;
    int dst = load_idx(ei, E + e);
    if ((unsigned)dst < (unsigned)M) atomicAdd(&deg[dst], 1);
}

__global__ void __launch_bounds__(1024) scan_kernel(
    const int* __restrict__ deg, int* __restrict__ off, int* __restrict__ pos, int n) {
    __shared__ int s[1024];
    int t = threadIdx.x;
    int chunk = (n + 1023) / 1024;
    int base = t * chunk;
    int sum = 0;
    for (int i = 0; i < chunk; i++) {
        int idx = base + i;
        if (idx < n) sum += deg[idx];
    }
    s[t] = sum;
    __syncthreads();
    for (int d = 1; d < 1024; d <<= 1) {
        int u = (t >= d) ? s[t - d] : 0;
        __syncthreads();
        s[t] += u;
        __syncthreads();
    }
    int run = s[t] - sum;
    for (int i = 0; i < chunk; i++) {
        int idx = base + i;
        if (idx < n) {
            off[idx] = run;
            pos[idx] = run;
            run += deg[idx];
        }
    }
    if (t == 1023) off[n] = s[1023];
}

__global__ void scatter_kernel(const void* __restrict__ ei, int* __restrict__ pos,
                               int* __restrict__ csr, int E, int M) {
    int e = blockIdx.x * blockDim.x + threadIdx.x;
    if (e >= E) return;
    int src = load_idx(ei, e);
    int dst = load_idx(ei, E + e);
    if ((unsigned)dst >= (unsigned)M || (unsigned)src >= (unsigned)M) return;
    int p = atomicAdd(&pos[dst], 1);
    csr[p] = src;
}

// split fp32 -> fp16 hi/lo (4 elems/thread)
__global__ void split_a_kernel(const float* __restrict__ src,
                               __half* __restrict__ hi,
                               __half* __restrict__ lo, int n4) {
    int i = blockIdx.x * blockDim.x + threadIdx.x;
    int s = gridDim.x * blockDim.x;
    for (; i < n4; i += s) {
        float4 v = ((const float4*)src)[i];
        __half h0 = __float2half_rn(v.x), h1 = __float2half_rn(v.y);
        __half h2 = __float2half_rn(v.z), h3 = __float2half_rn(v.w);
        __half l0 = __float2half_rn(v.x - __half2float(h0));
        __half l1 = __float2half_rn(v.y - __half2float(h1));
        __half l2 = __float2half_rn(v.z - __half2float(h2));
        __half l3 = __float2half_rn(v.w - __half2float(h3));
        ((__half2*)hi)[i * 2]     = __halves2half2(h0, h1);
        ((__half2*)hi)[i * 2 + 1] = __halves2half2(h2, h3);
        ((__half2*)lo)[i * 2]     = __halves2half2(l0, l1);
        ((__half2*)lo)[i * 2 + 1] = __halves2half2(l2, l3);
    }
}

struct WPtrs { const float* w[8]; const float* b[8]; };

__global__ void prep_weights(WPtrs P, __half* __restrict__ btf) {
    const float* W = P.w[blockIdx.z];
    int layer = blockIdx.z >> 2, j = blockIdx.z & 3;
    __shared__ float t[32][33];
    int tx = threadIdx.x, ty = threadIdx.y;
    int c0 = blockIdx.x * 32, k0 = blockIdx.y * 32;
#pragma unroll
    for (int r = 0; r < 4; r++) {
        int k = k0 + ty + r * 8;
        t[ty + r * 8][tx] = W[k * 256 + c0 + tx];
    }
    __syncthreads();
#pragma unroll
    for (int r = 0; r < 4; r++) {
        int c = c0 + ty + r * 8;
        int k = k0 + tx;
        size_t o = ((size_t)layer * 1024 + j * 256 + c) * 256 + k;
        btf[o] = __float2half_rn(t[tx][ty + r * 8]);
    }
}

__global__ void prep_bias(WPtrs P, float* __restrict__ biasc) {
    int idx = blockIdx.x * blockDim.x + threadIdx.x;
    if (idx < 2048) {
        int layer = idx >> 10, j = (idx >> 8) & 3, c = idx & 255;
        biasc[idx] = P.b[layer * 4 + j][c];
    }
}

// == mma.sync fp16 GEMM, 2-pass (A hi/lo fp16, B fp16), CTA 128x64, 2 CTA/SM ==
#define KPAD 72
#define A_TILE_B (128 * KPAD)                   // halves per A tile
#define B_TILE_B (64 * KPAD)                    // halves per B tile
#define STAGE_B (2 * A_TILE_B + B_TILE_B)       // Ah, Al, B
#define SM_BYTES (2 * STAGE_B * 2)              // 92160 bytes -> 2 CTAs/SM
#define GTHREADS 128

__device__ __forceinline__ void mma16816h(float* d, const uint32_t* a,
                                           const uint32_t* b) {
    asm volatile(
        "mma.sync.aligned.m16n8k16.row.col.f32.f16.f16.f32 "
        "{%0,%1,%2,%3}, {%4,%5,%6,%7}, {%8,%9}, {%0,%1,%2,%3};"
        : "+f"(d[0]), "+f"(d[1]), "+f"(d[2]), "+f"(d[3])
        : "r"(a[0]), "r"(a[1]), "r"(a[2]), "r"(a[3]), "r"(b[0]), "r"(b[1]));
}

__device__ __forceinline__ void cpa16(uint32_t dst_s, const void* src, bool valid) {
    int sz = valid ? 16 : 0;
    asm volatile("cp.async.cg.shared.global [%0], [%1], 16, %2;"
                 :: "r"(dst_s), "l"(src), "r"(sz));
}

__device__ __forceinline__ void load_tile_a(
    uint32_t s, const __half* __restrict__ g,
    int row0, int rowlim, int k0, int tid) {
#pragma unroll
    for (int it = 0; it < 8; it++) {
        int idx = it * GTHREADS + tid;
        int row = idx >> 3;
        int c8  = (idx & 7) * 8;
        int r = row0 + row;
        cpa16(s + (row * KPAD + c8) * 2, g + (size_t)r * 256 + k0 + c8, r < rowlim);
    }
}

__device__ __forceinline__ void load_tile_b(
    uint32_t s, const __half* __restrict__ g, int k0, int tid) {
#pragma unroll
    for (int it = 0; it < 4; it++) {
        int idx = it * GTHREADS + tid;
        int row = idx >> 3;
        int c8  = (idx & 7) * 8;
        cpa16(s + (row * KPAD + c8) * 2, g + (size_t)row * 256 + k0 + c8, true);
    }
}

__device__ __forceinline__ void issue_stage(
    uint32_t sb, int stage,
    const __half* ahi, const __half* alo, const __half* bt,
    int m0, int M, int k0, int tid) {
    uint32_t s = sb + stage * STAGE_B * 2;
    load_tile_a(s,                ahi, m0, M, k0, tid);
    load_tile_a(s + A_TILE_B * 2, alo, m0, M, k0, tid);
    load_tile_b(s + A_TILE_B * 4, bt, k0, tid);
    asm volatile("cp.async.commit_group;");
}

__global__ void __launch_bounds__(GTHREADS, 2) gemm_mma(
    const __half* __restrict__ ahi, const __half* __restrict__ alo,
    const __half* __restrict__ btf, const float* __restrict__ bias,
    float* __restrict__ qs_out, __half* __restrict__ kv_out, int M)
{
    extern __shared__ __align__(16) __half sm[];
    uint32_t sb = (uint32_t)__cvta_generic_to_shared(sm);

    const int tid = threadIdx.x;
    const int wid = tid >> 5, lane = tid & 31;
    const int wm = wid & 1, wn = wid >> 1;     // 2x2 warp grid
    const int g = lane >> 2, t = lane & 3;
    const int nt = blockIdx.x;                 // 0..15 : 64-col block
    const int m0 = blockIdx.y * 128;

    const __half* bt = btf + (size_t)nt * 64 * 256;

    float acc[4][4][4];
#pragma unroll
    for (int i = 0; i < 4; i++)
#pragma unroll
        for (int j = 0; j < 4; j++)
#pragma unroll
            for (int k = 0; k < 4; k++) acc[i][j][k] = 0.f;

    issue_stage(sb, 0, ahi, alo, bt, m0, M, 0, tid);

    for (int kc = 0; kc < 4; kc++) {
        if (kc + 1 < 4) {
            issue_stage(sb, (kc + 1) & 1, ahi, alo, bt, m0, M, (kc + 1) * 64, tid);
            asm volatile("cp.async.wait_group 1;");
        } else {
            asm volatile("cp.async.wait_group 0;");
        }
        __syncthreads();

        const __half* sAh = sm + (kc & 1) * STAGE_B;
        const __half* sAl = sAh + A_TILE_B;
        const __half* sB  = sAh + 2 * A_TILE_B;

#pragma unroll
        for (int ks = 0; ks < 4; ks++) {
            const int kb = ks * 16 + t * 2;
            uint32_t a_h[4][4], a_l[4][4];
#pragma unroll
            for (int mf = 0; mf < 4; mf++) {
                int r = wm * 64 + mf * 16 + g;
                a_h[mf][0] = *(const uint32_t*)(sAh + r * KPAD + kb);
                a_h[mf][1] = *(const uint32_t*)(sAh + (r + 8) * KPAD + kb);
                a_h[mf][2] = *(const uint32_t*)(sAh + r * KPAD + kb + 8);
                a_h[mf][3] = *(const uint32_t*)(sAh + (r + 8) * KPAD + kb + 8);
                a_l[mf][0] = *(const uint32_t*)(sAl + r * KPAD + kb);
                a_l[mf][1] = *(const uint32_t*)(sAl + (r + 8) * KPAD + kb);
                a_l[mf][2] = *(const uint32_t*)(sAl + r * KPAD + kb + 8);
                a_l[mf][3] = *(const uint32_t*)(sAl + (r + 8) * KPAD + kb + 8);
            }
#pragma unroll
            for (int nf = 0; nf < 4; nf++) {
                int c = wn * 32 + nf * 8 + g;
                uint32_t b_f[2];
                b_f[0] = *(const uint32_t*)(sB + c * KPAD + kb);
                b_f[1] = *(const uint32_t*)(sB + c * KPAD + kb + 8);
#pragma unroll
                for (int mf = 0; mf < 4; mf++) {
                    mma16816h(acc[mf][nf], a_h[mf], b_f);
                    mma16816h(acc[mf][nf], a_l[mf], b_f);
                }
            }
        }
        __syncthreads();
    }

    // epilogue: nt 0-3 -> q (fp32), nt 4-11 -> k|v (fp16), nt 12-15 -> s (fp32)
    const bool is_kv = (nt >= 4) && (nt < 12);
#pragma unroll
    for (int mf = 0; mf < 4; mf++) {
        int r0 = m0 + wm * 64 + mf * 16 + g;
#pragma unroll
        for (int nf = 0; nf < 4; nf++) {
            int cg = nt * 64 + wn * 32 + nf * 8 + t * 2;
            float bx = bias[cg], by = bias[cg + 1];
            float v0x = acc[mf][nf][0] + bx, v0y = acc[mf][nf][1] + by;
            float v1x = acc[mf][nf][2] + bx, v1y = acc[mf][nf][3] + by;
            if (is_kv) {
                int kc2 = cg - 256;
                if (r0 < M)
                    *(__half2*)(kv_out + (size_t)r0 * 512 + kc2) = __floats2half2_rn(v0x, v0y);
                if (r0 + 8 < M)
                    *(__half2*)(kv_out + (size_t)(r0 + 8) * 512 + kc2) = __floats2half2_rn(v1x, v1y);
            } else {
                int qc = (nt < 4) ? cg : cg - 512;
                if (r0 < M)
                    *(float2*)(qs_out + (size_t)r0 * 512 + qc) = make_float2(v0x, v0y);
                if (r0 + 8 < M)
                    *(float2*)(qs_out + (size_t)(r0 + 8) * 512 + qc) = make_float2(v1x, v1y);
            }
        }
    }
}

// ======= gather edge aggregation (2-edge unroll, fp16 k/v, barrier-free) ====
__device__ __forceinline__ float dot8h(const uint4& k, const float4& q0, const float4& q1) {
    const __half2* h = (const __half2*)&k;
    float2 f0 = __half22float2(h[0]);
    float2 f1 = __half22float2(h[1]);
    float2 f2 = __half22float2(h[2]);
    float2 f3 = __half22float2(h[3]);
    return q0.x * f0.x + q0.y * f0.y + q0.z * f1.x + q0.w * f1.y
         + q1.x * f2.x + q1.y * f2.y + q1.z * f3.x + q1.w * f3.y;
}

__device__ __forceinline__ void acc8h(const uint4& v, float ex,
                                      float* a0, float* a1) {
    const __half2* h = (const __half2*)&v;
    float2 f0 = __half22float2(h[0]);
    float2 f1 = __half22float2(h[1]);
    float2 f2 = __half22float2(h[2]);
    float2 f3 = __half22float2(h[3]);
    a0[0] += f0.x * ex; a0[1] += f0.y * ex; a0[2] += f1.x * ex; a0[3] += f1.y * ex;
    a1[0] += f2.x * ex; a1[1] += f2.y * ex; a1[2] += f3.x * ex; a1[3] += f3.y * ex;
}

__global__ void __launch_bounds__(256) edge_agg(
    const float* __restrict__ qs, const __half* __restrict__ kv,
    const int* __restrict__ off, const int* __restrict__ csr,
    float* __restrict__ accum, int M)
{
    int warp = (blockIdx.x * blockDim.x + threadIdx.x) >> 5;
    int lane = threadIdx.x & 31;
    if (warp >= M) return;

    const float4* qp = (const float4*)(qs + (size_t)warp * 512);
    float4 q0 = __ldg(&qp[lane * 2]), q1 = __ldg(&qp[lane * 2 + 1]);

    int i0 = off[warp], i1 = off[warp + 1];
    float a0[4] = {0.f, 0.f, 0.f, 0.f};
    float a1[4] = {0.f, 0.f, 0.f, 0.f};
    float dsum = 0.f;

    int i = i0;
    for (; i + 2 <= i1; i += 2) {
        int sa = __ldg(&csr[i]), sb = __ldg(&csr[i + 1]);
        const __half* pa = kv + (size_t)sa * 512 + lane * 8;
        const __half* pb = kv + (size_t)sb * 512 + lane * 8;
        uint4 ka = __ldg((const uint4*)pa);
        uint4 kb = __ldg((const uint4*)pb);
        uint4 va = __ldg((const uint4*)(pa + 256));
        uint4 vb = __ldg((const uint4*)(pb + 256));

        float p_a = dot8h(ka, q0, q1);
        float p_b = dot8h(kb, q0, q1);
        p_a += __shfl_xor_sync(0xffffffffu, p_a, 1);
        p_b += __shfl_xor_sync(0xffffffffu, p_b, 1);
        p_a += __shfl_xor_sync(0xffffffffu, p_a, 2);
        p_b += __shfl_xor_sync(0xffffffffu, p_b, 2);
        p_a += __shfl_xor_sync(0xffffffffu, p_a, 4);
        p_b += __shfl_xor_sync(0xffffffffu, p_b, 4);
        float exa = __expf(p_a * 0.125f);
        float exb = __expf(p_b * 0.125f);
        dsum += exa + exb;
        acc8h(va, exa, a0, a1);
        acc8h(vb, exb, a0, a1);
    }
    if (i < i1) {
        int s = __ldg(&csr[i]);
        const __half* pk = kv + (size_t)s * 512 + lane * 8;
        uint4 k = __ldg((const uint4*)pk);
        uint4 v = __ldg((const uint4*)(pk + 256));
        float p = dot8h(k, q0, q1);
        p += __shfl_xor_sync(0xffffffffu, p, 1);
        p += __shfl_xor_sync(0xffffffffu, p, 2);
        p += __shfl_xor_sync(0xffffffffu, p, 4);
        float ex = __expf(p * 0.125f);
        dsum += ex;
        acc8h(v, ex, a0, a1);
    }

    float inv = (dsum > 0.f) ? (1.0f / dsum) : 0.f;
    const float4* sp = (const float4*)(qs + (size_t)warp * 512 + 256);
    float4 s0 = __ldg(&sp[lane * 2]), s1 = __ldg(&sp[lane * 2 + 1]);
    float4 o0 = make_float4(a0[0] * inv + s0.x, a0[1] * inv + s0.y,
                            a0[2] * inv + s0.z, a0[3] * inv + s0.w);
    float4 o1 = make_float4(a1[0] * inv + s1.x, a1[1] * inv + s1.y,
                            a1[2] * inv + s1.z, a1[3] * inv + s1.w);
    float4* op = (float4*)(accum + (size_t)warp * WIDTH + lane * 8);
    op[0] = o0;
    op[1] = o1;
}

// ================= BN stats ==================================================
#define FIN_ROWS 32
__global__ void __launch_bounds__(256) stats_kernel(
    const float* __restrict__ accum, float* __restrict__ stats, int M)
{
    const int c = threadIdx.x;
    const int r0 = blockIdx.x * FIN_ROWS;
    float s1 = 0.f, s2 = 0.f;
#pragma unroll 4
    for (int r = 0; r < FIN_ROWS; r++) {
        int n = r0 + r;
        if (n >= M) break;
        float v = accum[(size_t)n * WIDTH + c];
        s1 += v; s2 += v * v;
    }
    atomicAdd(&stats[c], s1);
    atomicAdd(&stats[WIDTH + c], s2);
}

__global__ void __launch_bounds__(256) bn_act(
    const float* __restrict__ in, const float* __restrict__ stats,
    const float* __restrict__ gamma, const float* __restrict__ beta,
    float* __restrict__ out, int M, float invN)
{
    int idx = blockIdx.x * blockDim.x + threadIdx.x;
    int total = M * WIDTH;
    int stride = gridDim.x * blockDim.x;
    for (; idx < total; idx += stride) {
        int c = idx & (WIDTH - 1);
        float mean = stats[c] * invN;
        float var  = stats[WIDTH + c] * invN - mean * mean;
        float sc = rsqrtf(var + 1e-5f) * gamma[c];
        float sh = beta[c] - mean * sc;
        float v = in[idx] * sc + sh;
        out[idx] = (v >= 0.f) ? v : 0.1f * v;
    }
}

// BN + leaky-relu + fp16 hi/lo split, feeding the next GEMM directly
__global__ void __launch_bounds__(256) bn_act_split(
    const float* __restrict__ in, const float* __restrict__ stats,
    const float* __restrict__ gamma, const float* __restrict__ beta,
    __half* __restrict__ hi, __half* __restrict__ lo,
    int n4, float invN)
{
    int i = blockIdx.x * blockDim.x + threadIdx.x;
    int stride = gridDim.x * blockDim.x;
    for (; i < n4; i += stride) {
        int c = (i & 63) * 4;
        float4 v = ((const float4*)in)[i];
        float r[4] = {v.x, v.y, v.z, v.w};
        __half hh[4], ll[4];
#pragma unroll
        for (int j = 0; j < 4; j++) {
            int cc = c + j;
            float mean = stats[cc] * invN;
            float var  = stats[WIDTH + cc] * invN - mean * mean;
            float sc = rsqrtf(var + 1e-5f) * gamma[cc];
            float sh = beta[cc] - mean * sc;
            float x = r[j] * sc + sh;
            x = (x >= 0.f) ? x : 0.1f * x;
            hh[j] = __float2half_rn(x);
            ll[j] = __float2half_rn(x - __half2float(hh[j]));
        }
        ((__half2*)hi)[i * 2]     = __halves2half2(hh[0], hh[1]);
        ((__half2*)hi)[i * 2 + 1] = __halves2half2(hh[2], hh[3]);
        ((__half2*)lo)[i * 2]     = __halves2half2(ll[0], ll[1]);
        ((__half2*)lo)[i * 2 + 1] = __halves2half2(ll[2], ll[3]);
    }
}

// ================= launch ====================================================
extern "C" void kernel_launch(void* const* d_in, const int* in_sizes, int n_in,
                              void* d_out, int out_size)
{
    const float* x  = (const float*)d_in[0];
    const void*  ei = d_in[1];
    WPtrs wp;
    for (int i = 0; i < 4; i++) {
        wp.w[i]     = (const float*)d_in[2 + i * 2];
        wp.b[i]     = (const float*)d_in[3 + i * 2];
        wp.w[4 + i] = (const float*)d_in[12 + i * 2];
        wp.b[4 + i] = (const float*)d_in[13 + i * 2];
    }
    const float* g1  = (const float*)d_in[10]; const float* be1 = (const float*)d_in[11];
    const float* g2  = (const float*)d_in[20]; const float* be2 = (const float*)d_in[21];

    const int M = in_sizes[0] / WIDTH;   // 30000
    const int E = in_sizes[1] / 2;       // 600000

    float *qs, *accum, *stats, *biasc;
    __half *kv, *ahi, *alo, *btf;
    int *deg, *off, *pos, *csr;
    cudaGetSymbolAddress((void**)&qs,    g_qs);
    cudaGetSymbolAddress((void**)&kv,    g_kv);
    cudaGetSymbolAddress((void**)&accum, g_accum);
    cudaGetSymbolAddress((void**)&stats, g_stats);
    cudaGetSymbolAddress((void**)&ahi,   g_ahi);
    cudaGetSymbolAddress((void**)&alo,   g_alo);
    cudaGetSymbolAddress((void**)&btf,   g_btf);
    cudaGetSymbolAddress((void**)&biasc, g_biasc);
    cudaGetSymbolAddress((void**)&deg,   g_deg);
    cudaGetSymbolAddress((void**)&off,   g_off);
    cudaGetSymbolAddress((void**)&pos,   g_pos);
    cudaGetSymbolAddress((void**)&csr,   g_csr);

    cudaFuncSetAttribute(gemm_mma, cudaFuncAttributeMaxDynamicSharedMemorySize, SM_BYTES);

    dim3 ggrid(16, (M + 127) / 128);
    int eb = (E + 255) / 256;
    int agg_blocks  = (M * 32 + 255) / 256;
    int stat_blocks = (M + FIN_ROWS - 1) / FIN_ROWS;
    float invN = 1.0f / (float)M;

    // ---- prep (once, single stream) ----
    detect_idx_kernel<<<1, 512>>>((const int*)ei, 2 * E);
    prep_weights<<<dim3(8, 8, 8), dim3(32, 8)>>>(wp, btf);
    prep_bias<<<8, 256>>>(wp, biasc);
    cudaMemsetAsync(stats, 0, 4 * WIDTH * sizeof(float));   // both layers' stats

    // ---- CSR build (once) ----
    cudaMemsetAsync(deg, 0, M * sizeof(int));
    hist_kernel<<<eb, 256>>>(ei, deg, E, M);
    scan_kernel<<<1, 1024>>>(deg, off, pos, M);
    scatter_kernel<<<eb, 256>>>(ei, pos, csr, E, M);

    // ---- layer 1 ----
    split_a_kernel<<<960, 512>>>(x, ahi, alo, M * 64);
    gemm_mma<<<ggrid, GTHREADS, SM_BYTES>>>(ahi, alo, btf, biasc, qs, kv, M);
    edge_agg<<<agg_blocks, 256>>>(qs, kv, off, csr, accum, M);
    stats_kernel<<<stat_blocks, 256>>>(accum, stats, M);
    bn_act_split<<<480, 256>>>(accum, stats, g1, be1, ahi, alo, M * 64, invN);

    // ---- layer 2 ----
    gemm_mma<<<ggrid, GTHREADS, SM_BYTES>>>(ahi, alo, btf + (size_t)1024 * 256,
                                            biasc + 1024, qs, kv, M);
    edge_agg<<<agg_blocks, 256>>>(qs, kv, off, csr, accum, M);
    stats_kernel<<<stat_blocks, 256>>>(accum, stats + 2 * WIDTH, M);
    bn_act<<<480, 256>>>(accum, stats + 2 * WIDTH, g2, be2, (float*)d_out, M, invN);
}